// round 1
// baseline (speedup 1.0000x reference)
#include <cuda_runtime.h>
#include <math.h>

// ---------------------------------------------------------------------------
// BUTDDecoder: B=128, K=36, V_DIM=2048, EMBED=1024, HID=1024, NTOKEN=10000,
// MAX_LEN=20 (T=19 decode steps).
//
// Restructuring vs reference:
//  * gi1 const part ([v_mean, prev] @ Wih1[:,1024:].T) precomputed for all T
//  * word projection (W2) deferred to one big GEMM over all stored h2n[t]
//  * per-step: 6 small GEMMs + GRU pointwise + fused attention kernel
// ---------------------------------------------------------------------------

#define B_     128
#define KOBJ   36
#define VD     2048
#define EMB    1024
#define HID_   1024
#define NTOK   10000
#define MAXLEN 20
#define TT     19
#define H3     3072

// ------------------------- scratch (device globals) ------------------------
__device__ float g_vs[B_ * KOBJ * VD];          // permuted v            (37.7 MB)
__device__ float g_vmean[B_ * VD];              // mean over K           (1 MB)
__device__ float g_vproj[B_ * KOBJ * HID_];     // relu(v @ Wv.T + bv)   (18.9 MB)
__device__ float g_X1c[TT * B_ * H3];           // [v_mean | prev] rows  (29.9 MB)
__device__ float g_gi1c[TT * B_ * H3];          // const part of gi1     (29.9 MB)
__device__ float g_h1[B_ * HID_];
__device__ float g_h2all[(TT + 1) * B_ * HID_]; // slot 0 = zeros; slot t+1 = h2 after step t
__device__ float g_gih[B_ * H3];
__device__ float g_gh1[B_ * H3];
__device__ float g_X2[B_ * H3];                 // [att_v(2048) | hq(1024)]
__device__ float g_q[B_ * HID_];
__device__ float g_gi2[B_ * H3];
__device__ float g_gh2[B_ * H3];
__device__ int   g_order[B_];
__device__ int   g_dl[B_];
__device__ float g_mask[TT * B_];               // mask[t*B + b]

// ------------------------------ SGEMM (NT) ---------------------------------
// C[m,n] = sum_k A[m,k] * W[n,k] (+bias[n]) ; A row-major lda, W row-major ldw.
// mode 0: plain store; mode 1: relu; mode 2: scatter predict with mask:
//   m = t*B + b -> C[(b*MAXLEN + t)*ldc + n] = val * mask[m]
// Requirements: M % 64 == 0, Kd % 16 == 0, pointers 16B aligned. N guarded.
__global__ void __launch_bounds__(256) sgemm_nt(
    const float* __restrict__ A, int lda,
    const float* __restrict__ W, int ldw,
    float* __restrict__ C, int ldc,
    int N, int Kd,
    const float* __restrict__ bias,
    int mode, const float* __restrict__ mask)
{
    __shared__ float As[16][64];
    __shared__ float Ws[16][64];
    const int bn0 = blockIdx.x * 64;
    const int bm0 = blockIdx.y * 64;
    const int tid = threadIdx.x;
    const int lr  = tid >> 2;           // 0..63
    const int lk  = (tid & 3) << 2;     // 0,4,8,12
    const int tx  = tid & 15;
    const int ty  = tid >> 4;

    float acc[4][4];
#pragma unroll
    for (int i = 0; i < 4; i++)
#pragma unroll
        for (int j = 0; j < 4; j++) acc[i][j] = 0.f;

    const float* Aptr = A + (size_t)(bm0 + lr) * lda + lk;
    const int    wn   = bn0 + lr;
    const float* Wptr = W + (size_t)wn * ldw + lk;
    const bool   wvalid = (wn < N);

    for (int k0 = 0; k0 < Kd; k0 += 16) {
        float4 a4 = *(const float4*)(Aptr + k0);
        float4 w4 = wvalid ? *(const float4*)(Wptr + k0)
                           : make_float4(0.f, 0.f, 0.f, 0.f);
        As[lk + 0][lr] = a4.x; As[lk + 1][lr] = a4.y;
        As[lk + 2][lr] = a4.z; As[lk + 3][lr] = a4.w;
        Ws[lk + 0][lr] = w4.x; Ws[lk + 1][lr] = w4.y;
        Ws[lk + 2][lr] = w4.z; Ws[lk + 3][lr] = w4.w;
        __syncthreads();
#pragma unroll
        for (int kk = 0; kk < 16; kk++) {
            float ar[4], br[4];
#pragma unroll
            for (int i = 0; i < 4; i++) ar[i] = As[kk][ty * 4 + i];
#pragma unroll
            for (int j = 0; j < 4; j++) br[j] = Ws[kk][tx * 4 + j];
#pragma unroll
            for (int i = 0; i < 4; i++)
#pragma unroll
                for (int j = 0; j < 4; j++) acc[i][j] += ar[i] * br[j];
        }
        __syncthreads();
    }

#pragma unroll
    for (int i = 0; i < 4; i++) {
        int m = bm0 + ty * 4 + i;
#pragma unroll
        for (int j = 0; j < 4; j++) {
            int n = bn0 + tx * 4 + j;
            if (n >= N) continue;
            float val = acc[i][j];
            if (bias) val += bias[n];
            if (mode == 1) val = fmaxf(val, 0.f);
            if (mode == 2) {
                int t = m / B_, b = m % B_;
                C[((size_t)b * MAXLEN + t) * ldc + n] = val * mask[m];
            } else {
                C[(size_t)m * ldc + n] = val;
            }
        }
    }
}

// ------------------------------- small kernels -----------------------------

// Stable argsort (descending cap_len), decode lengths, and time masks.
__global__ void meta_kernel(const int* __restrict__ cap_len)
{
    int i = threadIdx.x;            // 128 threads
    int ci = cap_len[i];
    int rank = 0;
    for (int j = 0; j < B_; j++) {
        int cj = cap_len[j];
        if (cj > ci || (cj == ci && j < i)) rank++;
    }
    g_order[rank] = i;
    __syncthreads();
    g_dl[i] = cap_len[g_order[i]] - 1;
    __syncthreads();
    int dli = g_dl[i];
    for (int t = 0; t < TT; t++) g_mask[t * B_ + i] = (t < dli) ? 1.f : 0.f;
}

__global__ void zero_init_kernel()
{
    int idx = blockIdx.x * 256 + threadIdx.x;
    if (idx < B_ * HID_) {
        g_h1[idx] = 0.f;
        g_h2all[idx] = 0.f;   // h2 init (slot 0)
    }
}

__global__ void permute_v_kernel(const float* __restrict__ v)
{
    size_t idx = (size_t)blockIdx.x * 256 + threadIdx.x;
    if (idx >= (size_t)B_ * KOBJ * VD) return;
    int b = (int)(idx / ((size_t)KOBJ * VD));
    size_t rest = idx % ((size_t)KOBJ * VD);
    g_vs[idx] = v[(size_t)g_order[b] * KOBJ * VD + rest];
}

__global__ void vmean_kernel()
{
    int idx = blockIdx.x * 256 + threadIdx.x;
    if (idx >= B_ * VD) return;
    int b = idx / VD, d = idx % VD;
    const float* p = g_vs + (size_t)b * KOBJ * VD + d;
    float s = 0.f;
#pragma unroll 6
    for (int k = 0; k < KOBJ; k++) s += p[(size_t)k * VD];
    g_vmean[idx] = s * (1.f / (float)KOBJ);
}

// X1c rows (t*B+b): [v_mean[b] (2048) | caption[order[b], t, :] (1024)]
__global__ void build_x1c_kernel(const float* __restrict__ caption)
{
    size_t idx = (size_t)blockIdx.x * 256 + threadIdx.x;
    if (idx >= (size_t)TT * B_ * H3) return;
    int c = (int)(idx % H3);
    int r = (int)(idx / H3);
    int t = r / B_, b = r % B_;
    float val;
    if (c < VD) val = g_vmean[b * VD + c];
    else        val = caption[((size_t)g_order[b] * MAXLEN + t) * EMB + (c - VD)];
    g_X1c[idx] = val;
}

// GRU pointwise: h' = (1-z)*n + z*h ; gates ordered (r,z,n).
// gih nullable (extra additive input-gate contribution).
__global__ void gru_kernel(const float* __restrict__ gi,
                           const float* __restrict__ gih,
                           const float* __restrict__ gh,
                           const float* __restrict__ hprev,
                           float* __restrict__ hout)
{
    int idx = blockIdx.x * 256 + threadIdx.x;
    if (idx >= B_ * HID_) return;
    int b = idx >> 10, j = idx & 1023;
    size_t base = (size_t)b * H3 + j;
    float gr = gi[base], gz = gi[base + HID_], gn = gi[base + 2 * HID_];
    if (gih) {
        gr += gih[base]; gz += gih[base + HID_]; gn += gih[base + 2 * HID_];
    }
    float r = 1.f / (1.f + expf(-(gr + gh[base])));
    float z = 1.f / (1.f + expf(-(gz + gh[base + HID_])));
    float n = tanhf(gn + r * gh[base + 2 * HID_]);
    hout[idx] = (1.f - z) * n + z * hprev[idx];
}

// Attention: logits[b,k] = sum_d vproj[b,k,d] * q[b,d] * wa[d] + ba
// softmax over k; write masked alphas; att_v -> X2[:, :2048].
__global__ void att_kernel(const float* __restrict__ q,
                           const float* __restrict__ wa,
                           const float* __restrict__ ba,
                           float* __restrict__ alphas, int t)
{
    int b = blockIdx.x, tid = threadIdx.x;
    __shared__ float qs[HID_];
    __shared__ float att[KOBJ];
    for (int d = tid; d < HID_; d += 256) qs[d] = q[b * HID_ + d] * wa[d];
    __syncthreads();

    int warp = tid >> 5, lane = tid & 31;
    for (int k = warp; k < KOBJ; k += 8) {
        const float* vp = g_vproj + ((size_t)b * KOBJ + k) * HID_;
        float s = 0.f;
        for (int d = lane; d < HID_; d += 32) s += vp[d] * qs[d];
#pragma unroll
        for (int o = 16; o; o >>= 1) s += __shfl_down_sync(0xffffffffu, s, o);
        if (lane == 0) att[k] = s + ba[0];
    }
    __syncthreads();

    if (tid == 0) {
        float mx = att[0];
        for (int k = 1; k < KOBJ; k++) mx = fmaxf(mx, att[k]);
        float ssum = 0.f;
        for (int k = 0; k < KOBJ; k++) { float e = expf(att[k] - mx); att[k] = e; ssum += e; }
        float inv = 1.f / ssum;
        for (int k = 0; k < KOBJ; k++) att[k] *= inv;
    }
    __syncthreads();

    if (tid < KOBJ) {
        float m = (t < g_dl[b]) ? 1.f : 0.f;
        alphas[((size_t)b * MAXLEN + t) * KOBJ + tid] = att[tid] * m;
    }
    for (int d = tid; d < VD; d += 256) {
        const float* vb = g_vs + (size_t)b * KOBJ * VD + d;
        float s = 0.f;
#pragma unroll 6
        for (int k = 0; k < KOBJ; k++) s += att[k] * vb[(size_t)k * VD];
        g_X2[b * H3 + d] = s;
    }
}

// Zero padded last timestep (t = MAXLEN-1) of predict and alphas.
__global__ void zero_tails_kernel(float* __restrict__ predict,
                                  float* __restrict__ alphas)
{
    int idx = blockIdx.x * 256 + threadIdx.x;
    if (idx < B_ * NTOK) {
        int b = idx / NTOK, n = idx % NTOK;
        predict[((size_t)b * MAXLEN + (MAXLEN - 1)) * NTOK + n] = 0.f;
    } else if (idx < B_ * NTOK + B_ * KOBJ) {
        int r = idx - B_ * NTOK;
        int b = r / KOBJ, k = r % KOBJ;
        alphas[((size_t)b * MAXLEN + (MAXLEN - 1)) * KOBJ + k] = 0.f;
    }
}

// --------------------------------- launch ----------------------------------
extern "C" void kernel_launch(void* const* d_in, const int* in_sizes, int n_in,
                              void* d_out, int out_size)
{
    const float* v       = (const float*)d_in[0];
    const float* caption = (const float*)d_in[1];
    const int*   cap_len = (const int*)  d_in[2];
    const float* Wih1    = (const float*)d_in[3];
    const float* Whh1    = (const float*)d_in[4];
    const float* bih1    = (const float*)d_in[5];
    const float* bhh1    = (const float*)d_in[6];
    const float* Wih2    = (const float*)d_in[7];
    const float* Whh2    = (const float*)d_in[8];
    const float* bih2    = (const float*)d_in[9];
    const float* bhh2    = (const float*)d_in[10];
    const float* Wv      = (const float*)d_in[11];
    const float* bv      = (const float*)d_in[12];
    const float* Wq      = (const float*)d_in[13];
    const float* bq      = (const float*)d_in[14];
    const float* wa      = (const float*)d_in[15];
    const float* ba      = (const float*)d_in[16];
    const float* W1      = (const float*)d_in[17];
    const float* b1      = (const float*)d_in[18];
    const float* W2      = (const float*)d_in[19];
    const float* b2      = (const float*)d_in[20];

    float* out     = (float*)d_out;
    float* predict = out;                                   // [B, MAXLEN, NTOK]
    float* alphas  = out + (size_t)B_ * MAXLEN * NTOK;      // [B, MAXLEN, KOBJ]

    float *p_vs, *p_vproj, *p_X1c, *p_gi1c, *p_h1, *p_h2all;
    float *p_gih, *p_gh1, *p_X2, *p_q, *p_gi2, *p_gh2, *p_mask;
    cudaGetSymbolAddress((void**)&p_vs,    g_vs);
    cudaGetSymbolAddress((void**)&p_vproj, g_vproj);
    cudaGetSymbolAddress((void**)&p_X1c,   g_X1c);
    cudaGetSymbolAddress((void**)&p_gi1c,  g_gi1c);
    cudaGetSymbolAddress((void**)&p_h1,    g_h1);
    cudaGetSymbolAddress((void**)&p_h2all, g_h2all);
    cudaGetSymbolAddress((void**)&p_gih,   g_gih);
    cudaGetSymbolAddress((void**)&p_gh1,   g_gh1);
    cudaGetSymbolAddress((void**)&p_X2,    g_X2);
    cudaGetSymbolAddress((void**)&p_q,     g_q);
    cudaGetSymbolAddress((void**)&p_gi2,   g_gi2);
    cudaGetSymbolAddress((void**)&p_gh2,   g_gh2);
    cudaGetSymbolAddress((void**)&p_mask,  g_mask);

    // ---- setup ----
    meta_kernel<<<1, B_>>>(cap_len);
    zero_init_kernel<<<(B_ * HID_ + 255) / 256, 256>>>();
    {
        size_t n = (size_t)B_ * KOBJ * VD;
        permute_v_kernel<<<(unsigned)((n + 255) / 256), 256>>>(v);
    }
    vmean_kernel<<<(B_ * VD + 255) / 256, 256>>>();
    {
        size_t n = (size_t)TT * B_ * H3;
        build_x1c_kernel<<<(unsigned)((n + 255) / 256), 256>>>(caption);
    }

    // vproj = relu(v_s @ Wv.T + bv): [B*K, 2048] x [1024, 2048]
    {
        dim3 g(HID_ / 64, (B_ * KOBJ) / 64);
        sgemm_nt<<<g, 256>>>(p_vs, VD, Wv, VD, p_vproj, HID_,
                             HID_, VD, bv, 1, nullptr);
    }
    // gi1c = X1c @ Wih1[:,1024:].T + bih1: [T*B, 3072] x [3072, (ld 4096)]
    {
        dim3 g(H3 / 64, (TT * B_) / 64);
        sgemm_nt<<<g, 256>>>(p_X1c, H3, Wih1 + 1024, HID_ + VD + EMB,
                             p_gi1c, H3, H3, H3, bih1, 0, nullptr);
    }

    // ---- sequential decode ----
    dim3 gs(H3 / 64, B_ / 64);     // 48 x 2
    dim3 gh(HID_ / 64, B_ / 64);   // 16 x 2
    int gruBlocks = (B_ * HID_ + 255) / 256;

    for (int t = 0; t < TT; t++) {
        const float* h2prev = p_h2all + (size_t)t * B_ * HID_;
        float*       h2next = p_h2all + (size_t)(t + 1) * B_ * HID_;

        // gih = h2 @ Wih1[:, :1024].T
        sgemm_nt<<<gs, 256>>>(h2prev, HID_, Wih1, HID_ + VD + EMB,
                              p_gih, H3, H3, HID_, nullptr, 0, nullptr);
        // gh1 = h1 @ Whh1.T + bhh1
        sgemm_nt<<<gs, 256>>>(p_h1, HID_, Whh1, HID_,
                              p_gh1, H3, H3, HID_, bhh1, 0, nullptr);
        // h1 <- GRU1(h1)
        gru_kernel<<<gruBlocks, 256>>>(p_gi1c + (size_t)t * B_ * H3,
                                       p_gih, p_gh1, p_h1, p_h1);
        // hq = h1 @ W1.T + b1  -> X2[:, 2048:]
        sgemm_nt<<<gh, 256>>>(p_h1, HID_, W1, HID_,
                              p_X2 + VD, H3, HID_, HID_, b1, 0, nullptr);
        // q = relu(hq @ Wq.T + bq)
        sgemm_nt<<<gh, 256>>>(p_X2 + VD, H3, Wq, HID_,
                              p_q, HID_, HID_, HID_, bq, 1, nullptr);
        // attention -> alphas[:, t, :], att_v -> X2[:, :2048]
        att_kernel<<<B_, 256>>>(p_q, wa, ba, alphas, t);
        // gi2 = X2 @ Wih2.T + bih2
        sgemm_nt<<<gs, 256>>>(p_X2, H3, Wih2, H3,
                              p_gi2, H3, H3, H3, bih2, 0, nullptr);
        // gh2 = h2 @ Whh2.T + bhh2
        sgemm_nt<<<gs, 256>>>(h2prev, HID_, Whh2, HID_,
                              p_gh2, H3, H3, HID_, bhh2, 0, nullptr);
        // h2next <- GRU2(h2prev)
        gru_kernel<<<gruBlocks, 256>>>(p_gi2, nullptr, p_gh2, h2prev, h2next);
    }

    // words = H2all @ W2.T + b2, masked + scattered to predict[b, t, :]
    {
        dim3 g((NTOK + 63) / 64, (TT * B_) / 64);
        sgemm_nt<<<g, 256>>>(p_h2all + (size_t)B_ * HID_, HID_, W2, HID_,
                             predict, NTOK, NTOK, HID_, b2, 2, p_mask);
    }
    zero_tails_kernel<<<(B_ * NTOK + B_ * KOBJ + 255) / 256, 256>>>(predict, alphas);
}

// round 3
// speedup vs baseline: 1.4226x; 1.4226x over previous
#include <cuda_runtime.h>
#include <math.h>

// ---------------------------------------------------------------------------
// BUTDDecoder: B=128, K=36, V_DIM=2048, EMBED=1024, HID=1024, NTOKEN=10000,
// MAX_LEN=20 (T=19 decode steps).
//
// Round 3: Round-2 design with the A-fragment indexing bug fixed
// (dup-A float4 offset 4*ip, not 8*ip), dead hq GEMM removed.
// ---------------------------------------------------------------------------

#define B_     128
#define KOBJ   36
#define VD     2048
#define EMB    1024
#define HID_   1024
#define NTOK   10000
#define MAXLEN 20
#define TT     19
#define H3     3072

typedef unsigned long long ull;

// ------------------------- scratch (device globals) ------------------------
__device__ float g_vs[B_ * KOBJ * VD];
__device__ float g_vmean[B_ * VD];
__device__ float g_vproj[B_ * KOBJ * HID_];
__device__ float g_X1c[TT * B_ * H3];
__device__ float g_gi1c[TT * B_ * H3];
__device__ float g_h1[B_ * HID_];
__device__ float g_h2all[(TT + 1) * B_ * HID_];
__device__ float g_gih[B_ * H3];
__device__ float g_gh1[B_ * H3];
__device__ float g_gh2[B_ * H3];
__device__ float g_q[B_ * HID_];
__device__ float g_gi2h[B_ * H3];
__device__ float g_attv[B_ * VD];
__device__ float g_p0[B_ * H3];
__device__ float g_p1[B_ * H3];
__device__ float g_Wfq[HID_ * HID_];     // Wq @ W1
__device__ float g_Wf2h[H3 * HID_];      // Wih2[:,2048:] @ W1
__device__ float g_bfq[HID_];            // Wq@b1 + bq
__device__ float g_bi2f[H3];             // Wih2[:,2048:]@b1 + bih2
__device__ int   g_order[B_];
__device__ int   g_dl[B_];
__device__ float g_mask[TT * B_];

// --------------------------- f32x2 primitives -------------------------------
__device__ __forceinline__ ull pk2(float x, float y) {
    ull r; asm("mov.b64 %0, {%1, %2};" : "=l"(r) : "f"(x), "f"(y)); return r;
}
__device__ __forceinline__ void ffma2(ull& d, ull a, ull b) {
    asm("fma.rn.f32x2 %0, %1, %2, %0;" : "+l"(d) : "l"(a), "l"(b));
}
__device__ __forceinline__ float2 unpk(ull v) {
    float2 r; asm("mov.b64 {%0, %1}, %2;" : "=f"(r.x), "=f"(r.y) : "l"(v)); return r;
}

// ------------------------------ GEMM ----------------------------------------
// C[m,n] = sum_k A[m,k] * W[n,k]   (TB=true,  NT: W row-major [N,K], ldw)
// C[m,n] = sum_k A[m,k] * W[k,n]   (TB=false, NN: W row-major [K,N], ldw)
// mode 0: store (+bias); mode 1: relu(+bias); mode 2: masked scatter:
//   m = t*B+b -> C[(b*MAXLEN+t)*ldc + n] = (val+bias)*mask[m]
// Requirements: M % BM == 0, K % BK == 0. N guarded (TB path).
struct GemmZ {
    const float* A; const float* W; float* C; const float* bias;
    int lda, ldw, ldc, N, K, mode;
};
struct GemmP {
    GemmZ z[4];
    const float* mask;
};

template<int BM, int BN, int BK, int TM, int TN, bool TB>
__global__ void __launch_bounds__(256, 2) gemm_k(GemmP p)
{
    const GemmZ gz = p.z[blockIdx.z];
    const int bn0 = blockIdx.x * BN;
    if (bn0 >= gz.N) return;
    const int bm0 = blockIdx.y * BM;
    const int tid = threadIdx.x;

    __shared__ float As[BK][2 * BM];   // duplicated along m: (a,a) pairs
    __shared__ float Bs[BK][BN];

    constexpr int NTX = BN / TN;       // threads along n
    const int tx = tid % NTX;
    const int ty = tid / NTX;

    constexpr int FA = (BM * BK) / 1024;   // float4 per thread for A tile
    constexpr int FB = (BN * BK) / 1024;   // float4 per thread for B tile

    float4 pa[FA], pb[FB];
    const float* Abase = gz.A + (size_t)bm0 * gz.lda;

    // ---- initial gmem load (k0 = 0) ----
#pragma unroll
    for (int f = 0; f < FA; f++) {
        int q = tid * FA + f;
        int r = q >> 2, c4 = (q & 3) * 4;         // [BM][BK/4] (BK=16)
        pa[f] = *(const float4*)(Abase + (size_t)r * gz.lda + c4);
    }
    if (TB) {
#pragma unroll
        for (int f = 0; f < FB; f++) {
            int q = tid * FB + f;
            int r = q >> 2, c4 = (q & 3) * 4;     // [BN][BK/4]
            int n = bn0 + r;
            pb[f] = (n < gz.N) ? *(const float4*)(gz.W + (size_t)n * gz.ldw + c4)
                               : make_float4(0.f, 0.f, 0.f, 0.f);
        }
    } else {
#pragma unroll
        for (int f = 0; f < FB; f++) {
            int q = tid * FB + f;
            int r = q / (BN / 4), c = q % (BN / 4);   // [BK][BN/4]
            pb[f] = *(const float4*)(gz.W + (size_t)r * gz.ldw + bn0 + c * 4);
        }
    }

    ull acc[TM][TN / 2];
#pragma unroll
    for (int i = 0; i < TM; i++)
#pragma unroll
        for (int j = 0; j < TN / 2; j++) acc[i][j] = 0ULL;

    const int K = gz.K;
    for (int k0 = 0; k0 < K; k0 += BK) {
        // ---- stage regs -> smem ----
#pragma unroll
        for (int f = 0; f < FA; f++) {
            int q = tid * FA + f;
            int r = q >> 2, c4 = (q & 3) * 4;
            As[c4 + 0][2 * r] = pa[f].x; As[c4 + 0][2 * r + 1] = pa[f].x;
            As[c4 + 1][2 * r] = pa[f].y; As[c4 + 1][2 * r + 1] = pa[f].y;
            As[c4 + 2][2 * r] = pa[f].z; As[c4 + 2][2 * r + 1] = pa[f].z;
            As[c4 + 3][2 * r] = pa[f].w; As[c4 + 3][2 * r + 1] = pa[f].w;
        }
        if (TB) {
#pragma unroll
            for (int f = 0; f < FB; f++) {
                int q = tid * FB + f;
                int r = q >> 2, c4 = (q & 3) * 4;
                Bs[c4 + 0][r] = pb[f].x;
                Bs[c4 + 1][r] = pb[f].y;
                Bs[c4 + 2][r] = pb[f].z;
                Bs[c4 + 3][r] = pb[f].w;
            }
        } else {
#pragma unroll
            for (int f = 0; f < FB; f++) {
                int q = tid * FB + f;
                int r = q / (BN / 4), c = q % (BN / 4);
                *(float4*)&Bs[r][c * 4] = pb[f];
            }
        }
        __syncthreads();

        // ---- prefetch next chunk ----
        if (k0 + BK < K) {
            const float* An = Abase + (k0 + BK);
#pragma unroll
            for (int f = 0; f < FA; f++) {
                int q = tid * FA + f;
                int r = q >> 2, c4 = (q & 3) * 4;
                pa[f] = *(const float4*)(An + (size_t)r * gz.lda + c4);
            }
            if (TB) {
                const float* Wn = gz.W + (k0 + BK);
#pragma unroll
                for (int f = 0; f < FB; f++) {
                    int q = tid * FB + f;
                    int r = q >> 2, c4 = (q & 3) * 4;
                    int n = bn0 + r;
                    pb[f] = (n < gz.N) ? *(const float4*)(Wn + (size_t)n * gz.ldw + c4)
                                       : make_float4(0.f, 0.f, 0.f, 0.f);
                }
            } else {
                const float* Wn = gz.W + (size_t)(k0 + BK) * gz.ldw;
#pragma unroll
                for (int f = 0; f < FB; f++) {
                    int q = tid * FB + f;
                    int r = q / (BN / 4), c = q % (BN / 4);
                    pb[f] = *(const float4*)(Wn + (size_t)r * gz.ldw + bn0 + c * 4);
                }
            }
        }

        // ---- compute BK k-steps ----
#pragma unroll
        for (int kk = 0; kk < BK; kk++) {
            ull aa[TM], bb[TN / 2];
#pragma unroll
            for (int ip = 0; ip < TM / 2; ip++) {
                // dup space: thread rows occupy 2*TM consecutive floats;
                // float4 #ip covers rows 2ip, 2ip+1 -> offset 4*ip.
                float4 t = *(const float4*)&As[kk][2 * ty * TM + 4 * ip];
                aa[2 * ip]     = pk2(t.x, t.y);
                aa[2 * ip + 1] = pk2(t.z, t.w);
            }
#pragma unroll
            for (int jq = 0; jq < TN / 4; jq++) {
                float4 u = *(const float4*)&Bs[kk][tx * TN + 4 * jq];
                bb[2 * jq]     = pk2(u.x, u.y);
                bb[2 * jq + 1] = pk2(u.z, u.w);
            }
#pragma unroll
            for (int i = 0; i < TM; i++)
#pragma unroll
                for (int j = 0; j < TN / 2; j++)
                    ffma2(acc[i][j], aa[i], bb[j]);
        }
        __syncthreads();
    }

    // ---- epilogue ----
#pragma unroll
    for (int i = 0; i < TM; i++) {
        const int m = bm0 + ty * TM + i;
#pragma unroll
        for (int j = 0; j < TN / 2; j++) {
            float2 v = unpk(acc[i][j]);
            const int n = bn0 + tx * TN + 2 * j;
#pragma unroll
            for (int e = 0; e < 2; e++) {
                int ne = n + e;
                if (ne >= gz.N) continue;
                float val = (e == 0) ? v.x : v.y;
                if (gz.bias) val += gz.bias[ne];
                if (gz.mode == 1) val = fmaxf(val, 0.f);
                if (gz.mode == 2) {
                    int t = m / B_, b = m % B_;
                    gz.C[((size_t)b * MAXLEN + t) * gz.ldc + ne] = val * p.mask[m];
                } else {
                    gz.C[(size_t)m * gz.ldc + ne] = val;
                }
            }
        }
    }
}

// ------------------------------- small kernels -----------------------------
__global__ void meta_kernel(const int* __restrict__ cap_len)
{
    int i = threadIdx.x;
    int ci = cap_len[i];
    int rank = 0;
    for (int j = 0; j < B_; j++) {
        int cj = cap_len[j];
        if (cj > ci || (cj == ci && j < i)) rank++;
    }
    g_order[rank] = i;
    __syncthreads();
    g_dl[i] = cap_len[g_order[i]] - 1;
    __syncthreads();
    int dli = g_dl[i];
    for (int t = 0; t < TT; t++) g_mask[t * B_ + i] = (t < dli) ? 1.f : 0.f;
}

__global__ void zero_init_kernel()
{
    int idx = blockIdx.x * 256 + threadIdx.x;
    if (idx < B_ * HID_) {
        g_h1[idx] = 0.f;
        g_h2all[idx] = 0.f;
    }
}

__global__ void permute_v_kernel(const float* __restrict__ v)
{
    size_t idx = (size_t)blockIdx.x * 256 + threadIdx.x;
    if (idx >= (size_t)B_ * KOBJ * VD) return;
    int b = (int)(idx / ((size_t)KOBJ * VD));
    size_t rest = idx % ((size_t)KOBJ * VD);
    g_vs[idx] = v[(size_t)g_order[b] * KOBJ * VD + rest];
}

__global__ void vmean_kernel()
{
    int idx = blockIdx.x * 256 + threadIdx.x;
    if (idx >= B_ * VD) return;
    int b = idx / VD, d = idx % VD;
    const float* p = g_vs + (size_t)b * KOBJ * VD + d;
    float s = 0.f;
#pragma unroll 6
    for (int k = 0; k < KOBJ; k++) s += p[(size_t)k * VD];
    g_vmean[idx] = s * (1.f / (float)KOBJ);
}

__global__ void build_x1c_kernel(const float* __restrict__ caption)
{
    size_t idx = (size_t)blockIdx.x * 256 + threadIdx.x;
    if (idx >= (size_t)TT * B_ * H3) return;
    int c = (int)(idx % H3);
    int r = (int)(idx / H3);
    int t = r / B_, b = r % B_;
    float val;
    if (c < VD) val = g_vmean[b * VD + c];
    else        val = caption[((size_t)g_order[b] * MAXLEN + t) * EMB + (c - VD)];
    g_X1c[idx] = val;
}

// g_bfq[n]  = Wq[n,:]@b1 + bq[n]            (n < 1024)
// g_bi2f[n] = Wih2[n,2048:]@b1 + bih2[n]    (n < 3072)
__global__ void fusebias_kernel(const float* __restrict__ Wq,
                                const float* __restrict__ bq,
                                const float* __restrict__ b1,
                                const float* __restrict__ Wih2,
                                const float* __restrict__ bih2)
{
    int idx = blockIdx.x * 256 + threadIdx.x;
    if (idx < HID_) {
        const float* w = Wq + (size_t)idx * HID_;
        float s = 0.f;
        for (int j = 0; j < HID_; j++) s += w[j] * b1[j];
        g_bfq[idx] = s + bq[idx];
    } else if (idx < HID_ + H3) {
        int n = idx - HID_;
        const float* w = Wih2 + (size_t)n * H3 + VD;
        float s = 0.f;
        for (int j = 0; j < HID_; j++) s += w[j] * b1[j];
        g_bi2f[n] = s + bih2[n];
    }
}

// GRU pointwise: gi = gia + gib (+gic) (+biv) ; h' = (1-z)*n + z*h
__global__ void gru_kernel(const float* __restrict__ gia,
                           const float* __restrict__ gib,
                           const float* __restrict__ gic,
                           const float* __restrict__ biv,
                           const float* __restrict__ gh,
                           const float* __restrict__ hprev,
                           float* __restrict__ hout)
{
    int idx = blockIdx.x * 256 + threadIdx.x;
    if (idx >= B_ * HID_) return;
    int b = idx >> 10, j = idx & 1023;
    size_t base = (size_t)b * H3 + j;
    float gr = gia[base]            + gib[base];
    float gz = gia[base + HID_]     + gib[base + HID_];
    float gn = gia[base + 2 * HID_] + gib[base + 2 * HID_];
    if (gic) {
        gr += gic[base]; gz += gic[base + HID_]; gn += gic[base + 2 * HID_];
    }
    if (biv) {
        gr += biv[j]; gz += biv[j + HID_]; gn += biv[j + 2 * HID_];
    }
    float r = 1.f / (1.f + expf(-(gr + gh[base])));
    float z = 1.f / (1.f + expf(-(gz + gh[base + HID_])));
    float n = tanhf(gn + r * gh[base + 2 * HID_]);
    hout[idx] = (1.f - z) * n + z * hprev[idx];
}

// Attention: logits[b,k] = vproj[b,k,:] . (q[b,:]*wa) + ba ; softmax over k;
// masked alphas out; att_v -> g_attv.
__global__ void att_kernel(const float* __restrict__ wa,
                           const float* __restrict__ ba,
                           float* __restrict__ alphas, int t)
{
    int b = blockIdx.x, tid = threadIdx.x;
    __shared__ float qs[HID_];
    __shared__ float att[KOBJ];
    for (int d = tid; d < HID_; d += 256) qs[d] = g_q[b * HID_ + d] * wa[d];
    __syncthreads();

    int warp = tid >> 5, lane = tid & 31;
    for (int k = warp; k < KOBJ; k += 8) {
        const float* vp = g_vproj + ((size_t)b * KOBJ + k) * HID_;
        float s = 0.f;
        for (int d = lane; d < HID_; d += 32) s += vp[d] * qs[d];
#pragma unroll
        for (int o = 16; o; o >>= 1) s += __shfl_down_sync(0xffffffffu, s, o);
        if (lane == 0) att[k] = s + ba[0];
    }
    __syncthreads();

    if (tid == 0) {
        float mx = att[0];
        for (int k = 1; k < KOBJ; k++) mx = fmaxf(mx, att[k]);
        float ssum = 0.f;
        for (int k = 0; k < KOBJ; k++) { float e = expf(att[k] - mx); att[k] = e; ssum += e; }
        float inv = 1.f / ssum;
        for (int k = 0; k < KOBJ; k++) att[k] *= inv;
    }
    __syncthreads();

    if (tid < KOBJ) {
        float m = (t < g_dl[b]) ? 1.f : 0.f;
        alphas[((size_t)b * MAXLEN + t) * KOBJ + tid] = att[tid] * m;
    }
    for (int d = tid; d < VD; d += 256) {
        const float* vb = g_vs + (size_t)b * KOBJ * VD + d;
        float s = 0.f;
#pragma unroll 6
        for (int k = 0; k < KOBJ; k++) s += att[k] * vb[(size_t)k * VD];
        g_attv[b * VD + d] = s;
    }
}

__global__ void zero_tails_kernel(float* __restrict__ predict,
                                  float* __restrict__ alphas)
{
    int idx = blockIdx.x * 256 + threadIdx.x;
    if (idx < B_ * NTOK) {
        int b = idx / NTOK, n = idx % NTOK;
        predict[((size_t)b * MAXLEN + (MAXLEN - 1)) * NTOK + n] = 0.f;
    } else if (idx < B_ * NTOK + B_ * KOBJ) {
        int r = idx - B_ * NTOK;
        int b = r / KOBJ, k = r % KOBJ;
        alphas[((size_t)b * MAXLEN + (MAXLEN - 1)) * KOBJ + k] = 0.f;
    }
}

// --------------------------------- launch ----------------------------------
static inline GemmZ mkz(const float* A, int lda, const float* W, int ldw,
                        float* C, int ldc, int N, int K,
                        const float* bias, int mode)
{
    GemmZ z; z.A = A; z.W = W; z.C = C; z.bias = bias;
    z.lda = lda; z.ldw = ldw; z.ldc = ldc; z.N = N; z.K = K; z.mode = mode;
    return z;
}

extern "C" void kernel_launch(void* const* d_in, const int* in_sizes, int n_in,
                              void* d_out, int out_size)
{
    const float* v       = (const float*)d_in[0];
    const float* caption = (const float*)d_in[1];
    const int*   cap_len = (const int*)  d_in[2];
    const float* Wih1    = (const float*)d_in[3];
    const float* Whh1    = (const float*)d_in[4];
    const float* bih1    = (const float*)d_in[5];
    const float* bhh1    = (const float*)d_in[6];
    const float* Wih2    = (const float*)d_in[7];
    const float* Whh2    = (const float*)d_in[8];
    const float* bih2    = (const float*)d_in[9];
    const float* bhh2    = (const float*)d_in[10];
    const float* Wv      = (const float*)d_in[11];
    const float* bv      = (const float*)d_in[12];
    const float* Wq      = (const float*)d_in[13];
    const float* bq      = (const float*)d_in[14];
    const float* wa      = (const float*)d_in[15];
    const float* ba      = (const float*)d_in[16];
    const float* W1      = (const float*)d_in[17];
    const float* b1      = (const float*)d_in[18];
    const float* W2      = (const float*)d_in[19];
    const float* b2      = (const float*)d_in[20];

    float* out     = (float*)d_out;
    float* predict = out;
    float* alphas  = out + (size_t)B_ * MAXLEN * NTOK;

    float *p_vs, *p_vproj, *p_X1c, *p_gi1c, *p_h1, *p_h2all;
    float *p_gih, *p_gh1, *p_gh2, *p_q, *p_gi2h, *p_attv;
    float *p_p0, *p_p1, *p_Wfq, *p_Wf2h, *p_bfq, *p_bi2f, *p_mask;
    cudaGetSymbolAddress((void**)&p_vs,    g_vs);
    cudaGetSymbolAddress((void**)&p_vproj, g_vproj);
    cudaGetSymbolAddress((void**)&p_X1c,   g_X1c);
    cudaGetSymbolAddress((void**)&p_gi1c,  g_gi1c);
    cudaGetSymbolAddress((void**)&p_h1,    g_h1);
    cudaGetSymbolAddress((void**)&p_h2all, g_h2all);
    cudaGetSymbolAddress((void**)&p_gih,   g_gih);
    cudaGetSymbolAddress((void**)&p_gh1,   g_gh1);
    cudaGetSymbolAddress((void**)&p_gh2,   g_gh2);
    cudaGetSymbolAddress((void**)&p_q,     g_q);
    cudaGetSymbolAddress((void**)&p_gi2h,  g_gi2h);
    cudaGetSymbolAddress((void**)&p_attv,  g_attv);
    cudaGetSymbolAddress((void**)&p_p0,    g_p0);
    cudaGetSymbolAddress((void**)&p_p1,    g_p1);
    cudaGetSymbolAddress((void**)&p_Wfq,   g_Wfq);
    cudaGetSymbolAddress((void**)&p_Wf2h,  g_Wf2h);
    cudaGetSymbolAddress((void**)&p_bfq,   g_bfq);
    cudaGetSymbolAddress((void**)&p_bi2f,  g_bi2f);
    cudaGetSymbolAddress((void**)&p_mask,  g_mask);

    // ---- setup ----
    meta_kernel<<<1, B_>>>(cap_len);
    zero_init_kernel<<<(B_ * HID_ + 255) / 256, 256>>>();
    {
        size_t n = (size_t)B_ * KOBJ * VD;
        permute_v_kernel<<<(unsigned)((n + 255) / 256), 256>>>(v);
    }
    vmean_kernel<<<(B_ * VD + 255) / 256, 256>>>();
    {
        size_t n = (size_t)TT * B_ * H3;
        build_x1c_kernel<<<(unsigned)((n + 255) / 256), 256>>>(caption);
    }
    fusebias_kernel<<<(HID_ + H3 + 255) / 256, 256>>>(Wq, bq, b1, Wih2, bih2);

    // big GEMMs (BM=BN=128)
    {   // vproj = relu(v_s @ Wv.T + bv)
        GemmP P{}; P.mask = nullptr;
        P.z[0] = mkz(p_vs, VD, Wv, VD, p_vproj, HID_, HID_, VD, bv, 1);
        gemm_k<128,128,16,8,8,true><<<dim3(HID_/128, (B_*KOBJ)/128, 1), 256>>>(P);
    }
    {   // gi1c = X1c @ Wih1[:,1024:].T + bih1
        GemmP P{}; P.mask = nullptr;
        P.z[0] = mkz(p_X1c, H3, Wih1 + 1024, HID_ + VD + EMB, p_gi1c, H3, H3, H3, bih1, 0);
        gemm_k<128,128,16,8,8,true><<<dim3(H3/128, (TT*B_)/128, 1), 256>>>(P);
    }
    {   // Wfq = Wq @ W1  (NN)
        GemmP P{}; P.mask = nullptr;
        P.z[0] = mkz(Wq, HID_, W1, HID_, p_Wfq, HID_, HID_, HID_, nullptr, 0);
        gemm_k<128,128,16,8,8,false><<<dim3(HID_/128, HID_/128, 1), 256>>>(P);
    }
    {   // Wf2h = Wih2[:,2048:] @ W1  (NN), M=3072, N=1024
        GemmP P{}; P.mask = nullptr;
        P.z[0] = mkz(Wih2 + VD, H3, W1, HID_, p_Wf2h, HID_, HID_, HID_, nullptr, 0);
        gemm_k<128,128,16,8,8,false><<<dim3(HID_/128, H3/128, 1), 256>>>(P);
    }

    // ---- sequential decode ----
    const int gruBlocks = (B_ * HID_ + 255) / 256;
    for (int t = 0; t < TT; t++) {
        const float* h2prev = p_h2all + (size_t)t * B_ * HID_;
        float*       h2next = p_h2all + (size_t)(t + 1) * B_ * HID_;

        // stage1: gih = h2@Wih1[:,:1024].T ; gh1 = h1@Whh1.T+bhh1 ; gh2 = h2@Whh2.T+bhh2
        {
            GemmP P{}; P.mask = nullptr;
            P.z[0] = mkz(h2prev, HID_, Wih1, HID_ + VD + EMB, p_gih, H3, H3, HID_, nullptr, 0);
            P.z[1] = mkz(p_h1,   HID_, Whh1, HID_,            p_gh1, H3, H3, HID_, bhh1,   0);
            P.z[2] = mkz(h2prev, HID_, Whh2, HID_,            p_gh2, H3, H3, HID_, bhh2,   0);
            gemm_k<128,64,16,8,4,true><<<dim3(H3/64, 1, 3), 256>>>(P);
        }
        // GRU1 (h1 in-place)
        gru_kernel<<<gruBlocks, 256>>>(p_gi1c + (size_t)t * B_ * H3, p_gih,
                                       nullptr, nullptr, p_gh1, p_h1, p_h1);
        // stage2 (all from new h1): q = relu(h1@Wfq.T + bfq) ; gi2h = h1@Wf2h.T
        {
            GemmP P{}; P.mask = nullptr;
            P.z[0] = mkz(p_h1, HID_, p_Wfq,  HID_, p_q,    HID_, HID_, HID_, p_bfq,  1);
            P.z[1] = mkz(p_h1, HID_, p_Wf2h, HID_, p_gi2h, H3,   H3,   HID_, nullptr, 0);
            gemm_k<128,64,16,8,4,true><<<dim3(H3/64, 1, 2), 256>>>(P);
        }
        // attention -> alphas[:,t,:], att_v
        att_kernel<<<B_, 256>>>(wa, ba, alphas, t);
        // gi2_att = att_v @ Wih2[:,:2048].T, split-K = 2
        {
            GemmP P{}; P.mask = nullptr;
            P.z[0] = mkz(p_attv,        VD, Wih2,        H3, p_p0, H3, H3, HID_, nullptr, 0);
            P.z[1] = mkz(p_attv + 1024, VD, Wih2 + 1024, H3, p_p1, H3, H3, HID_, nullptr, 0);
            gemm_k<128,64,16,8,4,true><<<dim3(H3/64, 1, 2), 256>>>(P);
        }
        // GRU2: gi = p0 + p1 + gi2h + (bih2 + Wih2h@b1)
        gru_kernel<<<gruBlocks, 256>>>(p_p0, p_p1, p_gi2h, p_bi2f,
                                       p_gh2, h2prev, h2next);
    }

    // words = H2all @ W2.T + b2, masked scatter to predict[b,t,:]
    {
        GemmP P{}; P.mask = p_mask;
        P.z[0] = mkz(p_h2all + B_ * HID_, HID_, W2, HID_, predict, NTOK, NTOK, HID_, b2, 2);
        gemm_k<128,128,16,8,8,true><<<dim3((NTOK + 127) / 128, (TT*B_)/128, 1), 256>>>(P);
    }
    zero_tails_kernel<<<(B_ * NTOK + B_ * KOBJ + 255) / 256, 256>>>(predict, alphas);
}

// round 4
// speedup vs baseline: 1.4335x; 1.0077x over previous
#include <cuda_runtime.h>
#include <math.h>

// ---------------------------------------------------------------------------
// BUTDDecoder: B=128, K=36, V_DIM=2048, EMBED=1024, HID=1024, NTOKEN=10000,
// MAX_LEN=20 (T=19 decode steps).
//
// Round 4: f32x2 GEMM inner loop now loads (a,a)/(b0,b1) pairs directly as
// ld.shared.b64 (no pk2 packing movs), relieving issue slots and registers.
// Launch order rearranged so ncu (-s 5 -c 1) profiles the big gi1c GEMM.
// ---------------------------------------------------------------------------

#define B_     128
#define KOBJ   36
#define VD     2048
#define EMB    1024
#define HID_   1024
#define NTOK   10000
#define MAXLEN 20
#define TT     19
#define H3     3072

typedef unsigned long long ull;

// ------------------------- scratch (device globals) ------------------------
__device__ float g_vs[B_ * KOBJ * VD];
__device__ float g_vmean[B_ * VD];
__device__ float g_vproj[B_ * KOBJ * HID_];
__device__ float g_X1c[TT * B_ * H3];
__device__ float g_gi1c[TT * B_ * H3];
__device__ float g_h1[B_ * HID_];
__device__ float g_h2all[(TT + 1) * B_ * HID_];
__device__ float g_gih[B_ * H3];
__device__ float g_gh1[B_ * H3];
__device__ float g_gh2[B_ * H3];
__device__ float g_q[B_ * HID_];
__device__ float g_gi2h[B_ * H3];
__device__ float g_attv[B_ * VD];
__device__ float g_p0[B_ * H3];
__device__ float g_p1[B_ * H3];
__device__ float g_Wfq[HID_ * HID_];     // Wq @ W1
__device__ float g_Wf2h[H3 * HID_];      // Wih2[:,2048:] @ W1
__device__ float g_bfq[HID_];            // Wq@b1 + bq
__device__ float g_bi2f[H3];             // Wih2[:,2048:]@b1 + bih2
__device__ int   g_order[B_];
__device__ int   g_dl[B_];
__device__ float g_mask[TT * B_];

// --------------------------- f32x2 primitives -------------------------------
__device__ __forceinline__ void ffma2(ull& d, ull a, ull b) {
    asm("fma.rn.f32x2 %0, %1, %2, %0;" : "+l"(d) : "l"(a), "l"(b));
}
__device__ __forceinline__ float2 unpk(ull v) {
    float2 r; asm("mov.b64 {%0, %1}, %2;" : "=f"(r.x), "=f"(r.y) : "l"(v)); return r;
}

// ------------------------------ GEMM ----------------------------------------
// C[m,n] = sum_k A[m,k] * W[n,k]   (TB=true,  NT: W row-major [N,K], ldw)
// C[m,n] = sum_k A[m,k] * W[k,n]   (TB=false, NN: W row-major [K,N], ldw)
// mode 0: store (+bias); mode 1: relu(+bias); mode 2: masked scatter:
//   m = t*B+b -> C[(b*MAXLEN+t)*ldc + n] = (val+bias)*mask[m]
// Requirements: M % BM == 0 (per z grid-y coverage; early-out on gz.M),
// K % BK == 0. N guarded (TB path).
struct GemmZ {
    const float* A; const float* W; float* C; const float* bias;
    int lda, ldw, ldc, M, N, K, mode;
};
struct GemmP {
    GemmZ z[4];
    const float* mask;
};

template<int BM, int BN, int BK, int TM, int TN, bool TB>
__global__ void __launch_bounds__(256, 2) gemm_k(GemmP p)
{
    const GemmZ gz = p.z[blockIdx.z];
    const int bn0 = blockIdx.x * BN;
    if (bn0 >= gz.N) return;
    const int bm0 = blockIdx.y * BM;
    if (bm0 >= gz.M) return;
    const int tid = threadIdx.x;

    __shared__ float As[BK][2 * BM];   // duplicated along m: (a,a) pairs
    __shared__ float Bs[BK][BN];

    constexpr int NTX = BN / TN;       // threads along n
    const int tx = tid % NTX;
    const int ty = tid / NTX;

    constexpr int FA = (BM * BK) / 1024;   // float4 per thread for A tile
    constexpr int FB = (BN * BK) / 1024;   // float4 per thread for B tile

    float4 pa[FA], pb[FB];
    const float* Abase = gz.A + (size_t)bm0 * gz.lda;

    // ---- initial gmem load (k0 = 0) ----
#pragma unroll
    for (int f = 0; f < FA; f++) {
        int q = tid * FA + f;
        int r = q >> 2, c4 = (q & 3) * 4;         // [BM][BK/4] (BK=16)
        pa[f] = *(const float4*)(Abase + (size_t)r * gz.lda + c4);
    }
    if (TB) {
#pragma unroll
        for (int f = 0; f < FB; f++) {
            int q = tid * FB + f;
            int r = q >> 2, c4 = (q & 3) * 4;     // [BN][BK/4]
            int n = bn0 + r;
            pb[f] = (n < gz.N) ? *(const float4*)(gz.W + (size_t)n * gz.ldw + c4)
                               : make_float4(0.f, 0.f, 0.f, 0.f);
        }
    } else {
#pragma unroll
        for (int f = 0; f < FB; f++) {
            int q = tid * FB + f;
            int r = q / (BN / 4), c = q % (BN / 4);   // [BK][BN/4]
            pb[f] = *(const float4*)(gz.W + (size_t)r * gz.ldw + bn0 + c * 4);
        }
    }

    ull acc[TM][TN / 2];
#pragma unroll
    for (int i = 0; i < TM; i++)
#pragma unroll
        for (int j = 0; j < TN / 2; j++) acc[i][j] = 0ULL;

    const int K = gz.K;
    for (int k0 = 0; k0 < K; k0 += BK) {
        // ---- stage regs -> smem ----
#pragma unroll
        for (int f = 0; f < FA; f++) {
            int q = tid * FA + f;
            int r = q >> 2, c4 = (q & 3) * 4;
            As[c4 + 0][2 * r] = pa[f].x; As[c4 + 0][2 * r + 1] = pa[f].x;
            As[c4 + 1][2 * r] = pa[f].y; As[c4 + 1][2 * r + 1] = pa[f].y;
            As[c4 + 2][2 * r] = pa[f].z; As[c4 + 2][2 * r + 1] = pa[f].z;
            As[c4 + 3][2 * r] = pa[f].w; As[c4 + 3][2 * r + 1] = pa[f].w;
        }
        if (TB) {
#pragma unroll
            for (int f = 0; f < FB; f++) {
                int q = tid * FB + f;
                int r = q >> 2, c4 = (q & 3) * 4;
                Bs[c4 + 0][r] = pb[f].x;
                Bs[c4 + 1][r] = pb[f].y;
                Bs[c4 + 2][r] = pb[f].z;
                Bs[c4 + 3][r] = pb[f].w;
            }
        } else {
#pragma unroll
            for (int f = 0; f < FB; f++) {
                int q = tid * FB + f;
                int r = q / (BN / 4), c = q % (BN / 4);
                *(float4*)&Bs[r][c * 4] = pb[f];
            }
        }
        __syncthreads();

        // ---- prefetch next chunk ----
        if (k0 + BK < K) {
            const float* An = Abase + (k0 + BK);
#pragma unroll
            for (int f = 0; f < FA; f++) {
                int q = tid * FA + f;
                int r = q >> 2, c4 = (q & 3) * 4;
                pa[f] = *(const float4*)(An + (size_t)r * gz.lda + c4);
            }
            if (TB) {
                const float* Wn = gz.W + (k0 + BK);
#pragma unroll
                for (int f = 0; f < FB; f++) {
                    int q = tid * FB + f;
                    int r = q >> 2, c4 = (q & 3) * 4;
                    int n = bn0 + r;
                    pb[f] = (n < gz.N) ? *(const float4*)(Wn + (size_t)n * gz.ldw + c4)
                                       : make_float4(0.f, 0.f, 0.f, 0.f);
                }
            } else {
                const float* Wn = gz.W + (size_t)(k0 + BK) * gz.ldw;
#pragma unroll
                for (int f = 0; f < FB; f++) {
                    int q = tid * FB + f;
                    int r = q / (BN / 4), c = q % (BN / 4);
                    pb[f] = *(const float4*)(Wn + (size_t)r * gz.ldw + bn0 + c * 4);
                }
            }
        }

        // ---- compute BK k-steps: pairs loaded directly as b64 ----
#pragma unroll
        for (int kk = 0; kk < BK; kk++) {
            ull aa[TM], bb[TN / 2];
            const float* arow = &As[kk][2 * ty * TM];
            const float* brow = &Bs[kk][tx * TN];
#pragma unroll
            for (int i = 0; i < TM; i++)
                aa[i] = *(const ull*)(arow + 2 * i);      // (A[r], A[r])
#pragma unroll
            for (int j = 0; j < TN / 2; j++)
                bb[j] = *(const ull*)(brow + 2 * j);      // (B[n], B[n+1])
#pragma unroll
            for (int i = 0; i < TM; i++)
#pragma unroll
                for (int j = 0; j < TN / 2; j++)
                    ffma2(acc[i][j], aa[i], bb[j]);
        }
        __syncthreads();
    }

    // ---- epilogue ----
#pragma unroll
    for (int i = 0; i < TM; i++) {
        const int m = bm0 + ty * TM + i;
#pragma unroll
        for (int j = 0; j < TN / 2; j++) {
            float2 v = unpk(acc[i][j]);
            const int n = bn0 + tx * TN + 2 * j;
#pragma unroll
            for (int e = 0; e < 2; e++) {
                int ne = n + e;
                if (ne >= gz.N) continue;
                float val = (e == 0) ? v.x : v.y;
                if (gz.bias) val += gz.bias[ne];
                if (gz.mode == 1) val = fmaxf(val, 0.f);
                if (gz.mode == 2) {
                    int t = m / B_, b = m % B_;
                    gz.C[((size_t)b * MAXLEN + t) * gz.ldc + ne] = val * p.mask[m];
                } else {
                    gz.C[(size_t)m * gz.ldc + ne] = val;
                }
            }
        }
    }
}

// ------------------------------- small kernels -----------------------------
__global__ void meta_kernel(const int* __restrict__ cap_len)
{
    int i = threadIdx.x;
    int ci = cap_len[i];
    int rank = 0;
    for (int j = 0; j < B_; j++) {
        int cj = cap_len[j];
        if (cj > ci || (cj == ci && j < i)) rank++;
    }
    g_order[rank] = i;
    __syncthreads();
    g_dl[i] = cap_len[g_order[i]] - 1;
    __syncthreads();
    int dli = g_dl[i];
    for (int t = 0; t < TT; t++) g_mask[t * B_ + i] = (t < dli) ? 1.f : 0.f;
}

__global__ void zero_init_kernel()
{
    int idx = blockIdx.x * 256 + threadIdx.x;
    if (idx < B_ * HID_) {
        g_h1[idx] = 0.f;
        g_h2all[idx] = 0.f;
    }
}

__global__ void permute_v_kernel(const float* __restrict__ v)
{
    size_t idx = (size_t)blockIdx.x * 256 + threadIdx.x;
    if (idx >= (size_t)B_ * KOBJ * VD) return;
    int b = (int)(idx / ((size_t)KOBJ * VD));
    size_t rest = idx % ((size_t)KOBJ * VD);
    g_vs[idx] = v[(size_t)g_order[b] * KOBJ * VD + rest];
}

__global__ void vmean_kernel()
{
    int idx = blockIdx.x * 256 + threadIdx.x;
    if (idx >= B_ * VD) return;
    int b = idx / VD, d = idx % VD;
    const float* p = g_vs + (size_t)b * KOBJ * VD + d;
    float s = 0.f;
#pragma unroll 6
    for (int k = 0; k < KOBJ; k++) s += p[(size_t)k * VD];
    g_vmean[idx] = s * (1.f / (float)KOBJ);
}

__global__ void build_x1c_kernel(const float* __restrict__ caption)
{
    size_t idx = (size_t)blockIdx.x * 256 + threadIdx.x;
    if (idx >= (size_t)TT * B_ * H3) return;
    int c = (int)(idx % H3);
    int r = (int)(idx / H3);
    int t = r / B_, b = r % B_;
    float val;
    if (c < VD) val = g_vmean[b * VD + c];
    else        val = caption[((size_t)g_order[b] * MAXLEN + t) * EMB + (c - VD)];
    g_X1c[idx] = val;
}

// g_bfq[n]  = Wq[n,:]@b1 + bq[n]            (n < 1024)
// g_bi2f[n] = Wih2[n,2048:]@b1 + bih2[n]    (n < 3072)
__global__ void fusebias_kernel(const float* __restrict__ Wq,
                                const float* __restrict__ bq,
                                const float* __restrict__ b1,
                                const float* __restrict__ Wih2,
                                const float* __restrict__ bih2)
{
    int idx = blockIdx.x * 256 + threadIdx.x;
    if (idx < HID_) {
        const float* w = Wq + (size_t)idx * HID_;
        float s = 0.f;
        for (int j = 0; j < HID_; j++) s += w[j] * b1[j];
        g_bfq[idx] = s + bq[idx];
    } else if (idx < HID_ + H3) {
        int n = idx - HID_;
        const float* w = Wih2 + (size_t)n * H3 + VD;
        float s = 0.f;
        for (int j = 0; j < HID_; j++) s += w[j] * b1[j];
        g_bi2f[n] = s + bih2[n];
    }
}

// GRU pointwise: gi = gia + gib (+gic) (+biv) ; h' = (1-z)*n + z*h
__global__ void gru_kernel(const float* __restrict__ gia,
                           const float* __restrict__ gib,
                           const float* __restrict__ gic,
                           const float* __restrict__ biv,
                           const float* __restrict__ gh,
                           const float* __restrict__ hprev,
                           float* __restrict__ hout)
{
    int idx = blockIdx.x * 256 + threadIdx.x;
    if (idx >= B_ * HID_) return;
    int b = idx >> 10, j = idx & 1023;
    size_t base = (size_t)b * H3 + j;
    float gr = gia[base]            + gib[base];
    float gz = gia[base + HID_]     + gib[base + HID_];
    float gn = gia[base + 2 * HID_] + gib[base + 2 * HID_];
    if (gic) {
        gr += gic[base]; gz += gic[base + HID_]; gn += gic[base + 2 * HID_];
    }
    if (biv) {
        gr += biv[j]; gz += biv[j + HID_]; gn += biv[j + 2 * HID_];
    }
    float r = 1.f / (1.f + expf(-(gr + gh[base])));
    float z = 1.f / (1.f + expf(-(gz + gh[base + HID_])));
    float n = tanhf(gn + r * gh[base + 2 * HID_]);
    hout[idx] = (1.f - z) * n + z * hprev[idx];
}

// Attention: logits[b,k] = vproj[b,k,:] . (q[b,:]*wa) + ba ; softmax over k;
// masked alphas out; att_v -> g_attv.
__global__ void att_kernel(const float* __restrict__ wa,
                           const float* __restrict__ ba,
                           float* __restrict__ alphas, int t)
{
    int b = blockIdx.x, tid = threadIdx.x;
    __shared__ float qs[HID_];
    __shared__ float att[KOBJ];
    for (int d = tid; d < HID_; d += 256) qs[d] = g_q[b * HID_ + d] * wa[d];
    __syncthreads();

    int warp = tid >> 5, lane = tid & 31;
    for (int k = warp; k < KOBJ; k += 8) {
        const float* vp = g_vproj + ((size_t)b * KOBJ + k) * HID_;
        float s = 0.f;
        for (int d = lane; d < HID_; d += 32) s += vp[d] * qs[d];
#pragma unroll
        for (int o = 16; o; o >>= 1) s += __shfl_down_sync(0xffffffffu, s, o);
        if (lane == 0) att[k] = s + ba[0];
    }
    __syncthreads();

    if (tid == 0) {
        float mx = att[0];
        for (int k = 1; k < KOBJ; k++) mx = fmaxf(mx, att[k]);
        float ssum = 0.f;
        for (int k = 0; k < KOBJ; k++) { float e = expf(att[k] - mx); att[k] = e; ssum += e; }
        float inv = 1.f / ssum;
        for (int k = 0; k < KOBJ; k++) att[k] *= inv;
    }
    __syncthreads();

    if (tid < KOBJ) {
        float m = (t < g_dl[b]) ? 1.f : 0.f;
        alphas[((size_t)b * MAXLEN + t) * KOBJ + tid] = att[tid] * m;
    }
    for (int d = tid; d < VD; d += 256) {
        const float* vb = g_vs + (size_t)b * KOBJ * VD + d;
        float s = 0.f;
#pragma unroll 6
        for (int k = 0; k < KOBJ; k++) s += att[k] * vb[(size_t)k * VD];
        g_attv[b * VD + d] = s;
    }
}

__global__ void zero_tails_kernel(float* __restrict__ predict,
                                  float* __restrict__ alphas)
{
    int idx = blockIdx.x * 256 + threadIdx.x;
    if (idx < B_ * NTOK) {
        int b = idx / NTOK, n = idx % NTOK;
        predict[((size_t)b * MAXLEN + (MAXLEN - 1)) * NTOK + n] = 0.f;
    } else if (idx < B_ * NTOK + B_ * KOBJ) {
        int r = idx - B_ * NTOK;
        int b = r / KOBJ, k = r % KOBJ;
        alphas[((size_t)b * MAXLEN + (MAXLEN - 1)) * KOBJ + k] = 0.f;
    }
}

// --------------------------------- launch ----------------------------------
static inline GemmZ mkz(const float* A, int lda, const float* W, int ldw,
                        float* C, int ldc, int M, int N, int K,
                        const float* bias, int mode)
{
    GemmZ z; z.A = A; z.W = W; z.C = C; z.bias = bias;
    z.lda = lda; z.ldw = ldw; z.ldc = ldc; z.M = M; z.N = N; z.K = K; z.mode = mode;
    return z;
}

extern "C" void kernel_launch(void* const* d_in, const int* in_sizes, int n_in,
                              void* d_out, int out_size)
{
    const float* v       = (const float*)d_in[0];
    const float* caption = (const float*)d_in[1];
    const int*   cap_len = (const int*)  d_in[2];
    const float* Wih1    = (const float*)d_in[3];
    const float* Whh1    = (const float*)d_in[4];
    const float* bih1    = (const float*)d_in[5];
    const float* bhh1    = (const float*)d_in[6];
    const float* Wih2    = (const float*)d_in[7];
    const float* Whh2    = (const float*)d_in[8];
    const float* bih2    = (const float*)d_in[9];
    const float* bhh2    = (const float*)d_in[10];
    const float* Wv      = (const float*)d_in[11];
    const float* bv      = (const float*)d_in[12];
    const float* Wq      = (const float*)d_in[13];
    const float* bq      = (const float*)d_in[14];
    const float* wa      = (const float*)d_in[15];
    const float* ba      = (const float*)d_in[16];
    const float* W1      = (const float*)d_in[17];
    const float* b1      = (const float*)d_in[18];
    const float* W2      = (const float*)d_in[19];
    const float* b2      = (const float*)d_in[20];

    float* out     = (float*)d_out;
    float* predict = out;
    float* alphas  = out + (size_t)B_ * MAXLEN * NTOK;

    float *p_vs, *p_vproj, *p_X1c, *p_gi1c, *p_h1, *p_h2all;
    float *p_gih, *p_gh1, *p_gh2, *p_q, *p_gi2h, *p_attv;
    float *p_p0, *p_p1, *p_Wfq, *p_Wf2h, *p_bfq, *p_bi2f, *p_mask;
    cudaGetSymbolAddress((void**)&p_vs,    g_vs);
    cudaGetSymbolAddress((void**)&p_vproj, g_vproj);
    cudaGetSymbolAddress((void**)&p_X1c,   g_X1c);
    cudaGetSymbolAddress((void**)&p_gi1c,  g_gi1c);
    cudaGetSymbolAddress((void**)&p_h1,    g_h1);
    cudaGetSymbolAddress((void**)&p_h2all, g_h2all);
    cudaGetSymbolAddress((void**)&p_gih,   g_gih);
    cudaGetSymbolAddress((void**)&p_gh1,   g_gh1);
    cudaGetSymbolAddress((void**)&p_gh2,   g_gh2);
    cudaGetSymbolAddress((void**)&p_q,     g_q);
    cudaGetSymbolAddress((void**)&p_gi2h,  g_gi2h);
    cudaGetSymbolAddress((void**)&p_attv,  g_attv);
    cudaGetSymbolAddress((void**)&p_p0,    g_p0);
    cudaGetSymbolAddress((void**)&p_p1,    g_p1);
    cudaGetSymbolAddress((void**)&p_Wfq,   g_Wfq);
    cudaGetSymbolAddress((void**)&p_Wf2h,  g_Wf2h);
    cudaGetSymbolAddress((void**)&p_bfq,   g_bfq);
    cudaGetSymbolAddress((void**)&p_bi2f,  g_bi2f);
    cudaGetSymbolAddress((void**)&p_mask,  g_mask);

    // ---- setup (ordered so launch #6 = gi1c GEMM gets ncu'd) ----
    meta_kernel<<<1, B_>>>(cap_len);                                     // 1
    zero_init_kernel<<<(B_ * HID_ + 255) / 256, 256>>>();                // 2
    {
        size_t n = (size_t)B_ * KOBJ * VD;
        permute_v_kernel<<<(unsigned)((n + 255) / 256), 256>>>(v);       // 3
    }
    vmean_kernel<<<(B_ * VD + 255) / 256, 256>>>();                      // 4
    {
        size_t n = (size_t)TT * B_ * H3;
        build_x1c_kernel<<<(unsigned)((n + 255) / 256), 256>>>(caption); // 5
    }
    {   // 6: gi1c = X1c @ Wih1[:,1024:].T + bih1  (the 46-GF GEMM — profiled)
        GemmP P{}; P.mask = nullptr;
        P.z[0] = mkz(p_X1c, H3, Wih1 + 1024, HID_ + VD + EMB, p_gi1c, H3,
                     TT * B_, H3, H3, bih1, 0);
        gemm_k<128,128,16,8,8,true><<<dim3(H3/128, (TT*B_)/128, 1), 256>>>(P);
    }
    {   // vproj = relu(v_s @ Wv.T + bv)
        GemmP P{}; P.mask = nullptr;
        P.z[0] = mkz(p_vs, VD, Wv, VD, p_vproj, HID_, B_ * KOBJ, HID_, VD, bv, 1);
        gemm_k<128,128,16,8,8,true><<<dim3(HID_/128, (B_*KOBJ)/128, 1), 256>>>(P);
    }
    {   // precompute (z-batched): Wfq = Wq@W1 (M=1024) ; Wf2h = Wih2[:,2048:]@W1 (M=3072)
        GemmP P{}; P.mask = nullptr;
        P.z[0] = mkz(Wq,        HID_, W1, HID_, p_Wfq,  HID_, HID_, HID_, HID_, nullptr, 0);
        P.z[1] = mkz(Wih2 + VD, H3,   W1, HID_, p_Wf2h, HID_, H3,   HID_, HID_, nullptr, 0);
        gemm_k<128,128,16,8,8,false><<<dim3(HID_/128, H3/128, 2), 256>>>(P);
    }
    fusebias_kernel<<<(HID_ + H3 + 255) / 256, 256>>>(Wq, bq, b1, Wih2, bih2);

    // ---- sequential decode ----
    const int gruBlocks = (B_ * HID_ + 255) / 256;
    for (int t = 0; t < TT; t++) {
        const float* h2prev = p_h2all + (size_t)t * B_ * HID_;
        float*       h2next = p_h2all + (size_t)(t + 1) * B_ * HID_;

        // stage1: gih = h2@Wih1[:,:1024].T ; gh1 = h1@Whh1.T+bhh1 ; gh2 = h2@Whh2.T+bhh2
        {
            GemmP P{}; P.mask = nullptr;
            P.z[0] = mkz(h2prev, HID_, Wih1, HID_ + VD + EMB, p_gih, H3, B_, H3, HID_, nullptr, 0);
            P.z[1] = mkz(p_h1,   HID_, Whh1, HID_,            p_gh1, H3, B_, H3, HID_, bhh1,   0);
            P.z[2] = mkz(h2prev, HID_, Whh2, HID_,            p_gh2, H3, B_, H3, HID_, bhh2,   0);
            gemm_k<128,64,16,8,4,true><<<dim3(H3/64, 1, 3), 256>>>(P);
        }
        // GRU1 (h1 in-place)
        gru_kernel<<<gruBlocks, 256>>>(p_gi1c + (size_t)t * B_ * H3, p_gih,
                                       nullptr, nullptr, p_gh1, p_h1, p_h1);
        // stage2 (all from new h1): q = relu(h1@Wfq.T + bfq) ; gi2h = h1@Wf2h.T
        {
            GemmP P{}; P.mask = nullptr;
            P.z[0] = mkz(p_h1, HID_, p_Wfq,  HID_, p_q,    HID_, B_, HID_, HID_, p_bfq,  1);
            P.z[1] = mkz(p_h1, HID_, p_Wf2h, HID_, p_gi2h, H3,   B_, H3,   HID_, nullptr, 0);
            gemm_k<128,64,16,8,4,true><<<dim3(H3/64, 1, 2), 256>>>(P);
        }
        // attention -> alphas[:,t,:], att_v
        att_kernel<<<B_, 256>>>(wa, ba, alphas, t);
        // gi2_att = att_v @ Wih2[:,:2048].T, split-K = 2
        {
            GemmP P{}; P.mask = nullptr;
            P.z[0] = mkz(p_attv,        VD, Wih2,        H3, p_p0, H3, B_, H3, HID_, nullptr, 0);
            P.z[1] = mkz(p_attv + 1024, VD, Wih2 + 1024, H3, p_p1, H3, B_, H3, HID_, nullptr, 0);
            gemm_k<128,64,16,8,4,true><<<dim3(H3/64, 1, 2), 256>>>(P);
        }
        // GRU2: gi = p0 + p1 + gi2h + (bih2 + Wih2h@b1)
        gru_kernel<<<gruBlocks, 256>>>(p_p0, p_p1, p_gi2h, p_bi2f,
                                       p_gh2, h2prev, h2next);
    }

    // words = H2all @ W2.T + b2, masked scatter to predict[b,t,:]
    {
        GemmP P{}; P.mask = p_mask;
        P.z[0] = mkz(p_h2all + B_ * HID_, HID_, W2, HID_, predict, NTOK,
                     TT * B_, NTOK, HID_, b2, 2);
        gemm_k<128,128,16,8,8,true><<<dim3((NTOK + 127) / 128, (TT*B_)/128, 1), 256>>>(P);
    }
    zero_tails_kernel<<<(B_ * NTOK + B_ * KOBJ + 255) / 256, 256>>>(predict, alphas);
}

// round 7
// speedup vs baseline: 2.8444x; 1.9842x over previous
#include <cuda_runtime.h>
#include <cuda_bf16.h>
#include <math.h>

// ---------------------------------------------------------------------------
// BUTDDecoder: B=128, K=36, V_DIM=2048, EMBED=1024, HID=1024, NTOKEN=10000,
// MAX_LEN=20 (T=19 decode steps).
//
// Round 7: tcgen05 is not available under the harness's plain sm_103 PTX
// target. All NT GEMMs now use warp-level mma.sync.m16n8k16 bf16 (hi/lo x3
// split precision), ldmatrix with XOR-16B swizzle, and a 2-stage cp.async
// pipeline. SIMT f32x2 GEMM retained only for the two NN precompute GEMMs.
// ---------------------------------------------------------------------------

#define B_     128
#define KOBJ   36
#define VD     2048
#define EMB    1024
#define HID_   1024
#define NTOK   10000
#define MAXLEN 20
#define TT     19
#define H3     3072

typedef unsigned long long ull;
typedef __nv_bfloat16 bf16;

// ------------------------- scratch (device globals) ------------------------
__device__ float g_vs[B_ * KOBJ * VD];
__device__ float g_vmean[B_ * VD];
__device__ float g_vproj[B_ * KOBJ * HID_];
__device__ float g_gi1c[TT * B_ * H3];
__device__ float g_h1[B_ * HID_];
__device__ float g_h2all[(TT + 1) * B_ * HID_];
__device__ float g_gih[B_ * H3];
__device__ float g_gh1[B_ * H3];
__device__ float g_gh2[B_ * H3];
__device__ float g_q[B_ * HID_];
__device__ float g_gi2h[B_ * H3];
__device__ float g_p0[B_ * H3];
__device__ float g_Wfq[HID_ * HID_];     // Wq @ W1 (fp32, SIMT precompute)
__device__ float g_Wf2h[H3 * HID_];      // Wih2[:,2048:] @ W1
__device__ float g_bfq[HID_];            // Wq@b1 + bq
__device__ float g_bi2f[H3];             // Wih2[:,2048:]@b1 + bih2
__device__ int   g_order[B_];
__device__ int   g_dl[B_];
__device__ float g_mask[TT * B_];

// bf16 hi/lo operand arrays (activations)
__device__ bf16 g_vs_h[B_ * KOBJ * VD],        g_vs_l[B_ * KOBJ * VD];
__device__ bf16 g_x1c_h[TT * B_ * H3],         g_x1c_l[TT * B_ * H3];
__device__ bf16 g_h1_h[B_ * HID_],             g_h1_l[B_ * HID_];
__device__ bf16 g_h2_h[(TT + 1) * B_ * HID_],  g_h2_l[(TT + 1) * B_ * HID_];
__device__ bf16 g_attv_h[B_ * VD],             g_attv_l[B_ * VD];

// bf16 hi/lo weight arrays
__device__ bf16 g_wih1h_h[H3 * HID_],  g_wih1h_l[H3 * HID_];   // Wih1[:, :1024]
__device__ bf16 g_wih1x_h[H3 * H3],    g_wih1x_l[H3 * H3];     // Wih1[:, 1024:]
__device__ bf16 g_whh1_h[H3 * HID_],   g_whh1_l[H3 * HID_];
__device__ bf16 g_whh2_h[H3 * HID_],   g_whh2_l[H3 * HID_];
__device__ bf16 g_wv_h[HID_ * VD],     g_wv_l[HID_ * VD];
__device__ bf16 g_wih2v_h[H3 * VD],    g_wih2v_l[H3 * VD];     // Wih2[:, :2048]
__device__ bf16 g_w2_h[NTOK * HID_],   g_w2_l[NTOK * HID_];
__device__ bf16 g_wfq_h[HID_ * HID_],  g_wfq_l[HID_ * HID_];
__device__ bf16 g_wf2h_h[H3 * HID_],   g_wf2h_l[H3 * HID_];

// --------------------------- small helpers ---------------------------------
__device__ __forceinline__ void split2(float x, bf16& h, bf16& l) {
    h = __float2bfloat16(x);
    l = __float2bfloat16(x - __bfloat162float(h));
}
__device__ __forceinline__ unsigned smem_u32(const void* p) {
    return (unsigned)__cvta_generic_to_shared(p);
}
__device__ __forceinline__ void cpa16(unsigned dst, const void* src, int sz) {
    asm volatile("cp.async.ca.shared.global [%0], [%1], 16, %2;"
                 :: "r"(dst), "l"(src), "r"(sz));
}

#define LDM_X4(r0, r1, r2, r3, addr) \
    asm volatile("ldmatrix.sync.aligned.m8n8.x4.shared.b16 {%0,%1,%2,%3}, [%4];" \
        : "=r"(r0), "=r"(r1), "=r"(r2), "=r"(r3) : "r"(addr))

#define MMA16816(c, a, b) \
    asm volatile("mma.sync.aligned.m16n8k16.row.col.f32.bf16.bf16.f32 " \
        "{%0,%1,%2,%3}, {%4,%5,%6,%7}, {%8,%9}, {%0,%1,%2,%3};" \
        : "+f"((c)[0]), "+f"((c)[1]), "+f"((c)[2]), "+f"((c)[3]) \
        : "r"((a)[0]), "r"((a)[1]), "r"((a)[2]), "r"((a)[3]), \
          "r"((b)[0]), "r"((b)[1]))

// ----------------------------- tensor GEMM ---------------------------------
// C[m,n] = sum_k A[m,k]*W[n,k] with A = Ahi+Alo, W = Whi+Wlo (bf16 pairs).
// mode 0: +bias store; 1: relu(+bias); 2: masked scatter predict.
// Requires: M % 128 == 0, K % 64 == 0. N arbitrary (tail guarded).
struct TZ {
    const bf16 *Ahi, *Alo, *Whi, *Wlo;
    float* C; const float* bias;
    int lda, ldw, ldc, M, N, K, mode;
};
struct TP { TZ z[3]; const float* mask; };

// per-buffer smem: Ah 16K | Al 16K | Bh 8K | Bl 8K = 48K; two buffers = 96K
#define TGBUF 49152
#define TGSMEM (2 * TGBUF + 1024)

__global__ void __launch_bounds__(128) tgemm_k(TP p)
{
    const TZ gz = p.z[blockIdx.z];
    const int bn0 = blockIdx.x * 64;  if (bn0 >= gz.N) return;
    const int bm0 = blockIdx.y * 128; if (bm0 >= gz.M) return;
    const int tid = threadIdx.x, wid = tid >> 5, lane = tid & 31;
    const int wm = wid >> 1, wn = wid & 1;

    extern __shared__ char dsm[];
    unsigned dbase = smem_u32(dsm);
    unsigned s0 = (dbase + 1023u) & ~1023u;
    unsigned sAh[2], sAl[2], sBh[2], sBl[2];
#pragma unroll
    for (int b = 0; b < 2; b++) {
        sAh[b] = s0 + b * TGBUF;
        sAl[b] = sAh[b] + 16384;
        sBh[b] = sAl[b] + 16384;
        sBl[b] = sBh[b] + 8192;
    }

    // ---- coalesced cp.async chunk loader (BK=64 => 128B per row) ----
    const int lrow8 = tid >> 3;        // 0..15
    const int lch   = tid & 7;         // 16B chunk within row
    auto load_chunk = [&](int c, int buf) {
        const int c0 = c * 64;
        // A: 128 rows, 8 iterations x 16 rows, coalesced
#pragma unroll
        for (int i = 0; i < 8; i++) {
            int row = i * 16 + lrow8;
            unsigned off = (unsigned)(row * 128) + (unsigned)(((lch ^ (row & 7)) * 16));
            const bf16* sh = gz.Ahi + (size_t)(bm0 + row) * gz.lda + c0 + lch * 8;
            const bf16* sl = gz.Alo + (size_t)(bm0 + row) * gz.lda + c0 + lch * 8;
            cpa16(sAh[buf] + off, sh, 16);
            cpa16(sAl[buf] + off, sl, 16);
        }
        // B: 64 rows, 4 iterations x 16 rows, zero-fill tails
#pragma unroll
        for (int i = 0; i < 4; i++) {
            int row = i * 16 + lrow8;
            unsigned off = (unsigned)(row * 128) + (unsigned)(((lch ^ (row & 7)) * 16));
            int n = bn0 + row;
            int sz = (n < gz.N) ? 16 : 0;
            int nn = (n < gz.N) ? n : 0;
            const bf16* sh = gz.Whi + (size_t)nn * gz.ldw + c0 + lch * 8;
            const bf16* sl = gz.Wlo + (size_t)nn * gz.ldw + c0 + lch * 8;
            cpa16(sBh[buf] + off, sh, sz);
            cpa16(sBl[buf] + off, sl, sz);
        }
        asm volatile("cp.async.commit_group;");
    };

    float acc[4][4][4];
#pragma unroll
    for (int mi = 0; mi < 4; mi++)
#pragma unroll
        for (int nj = 0; nj < 4; nj++)
#pragma unroll
            for (int e = 0; e < 4; e++) acc[mi][nj][e] = 0.f;

    const int xorkey = lane & 7;
    const int nch = gz.K / 64;
    load_chunk(0, 0);

    for (int c = 0; c < nch; c++) {
        if (c + 1 < nch) {
            load_chunk(c + 1, (c + 1) & 1);
            asm volatile("cp.async.wait_group 1;");
        } else {
            asm volatile("cp.async.wait_group 0;");
        }
        __syncthreads();

        const unsigned tAh = sAh[c & 1], tAl = sAl[c & 1];
        const unsigned tBh = sBh[c & 1], tBl = sBl[c & 1];

#pragma unroll
        for (int ks = 0; ks < 4; ks++) {
            // ---- A fragments: 4 m-frags, hi+lo, ldmatrix.x4 non-trans ----
            unsigned Ah[4][4], Al[4][4];
            {
                const int arow = wm * 64 + (lane & 15);
                const unsigned aoff =
                    (unsigned)((((2 * ks) + (lane >> 4)) ^ xorkey) * 16);
#pragma unroll
                for (int mi = 0; mi < 4; mi++) {
                    unsigned ad = (unsigned)((arow + mi * 16) * 128) + aoff;
                    LDM_X4(Ah[mi][0], Ah[mi][1], Ah[mi][2], Ah[mi][3], tAh + ad);
                    LDM_X4(Al[mi][0], Al[mi][1], Al[mi][2], Al[mi][3], tAl + ad);
                }
            }
            // ---- B fragments: 4 n-frags, hi+lo ----
            unsigned Bh[4][2], Bl[4][2];
            {
                const int brow = wn * 32 + (lane & 7) + ((lane >> 4) << 3);
                const unsigned boff =
                    (unsigned)((((2 * ks) + ((lane >> 3) & 1)) ^ xorkey) * 16);
                unsigned r0, r1, r2, r3;
                unsigned b0 = (unsigned)(brow * 128) + boff;
                LDM_X4(r0, r1, r2, r3, tBh + b0);
                Bh[0][0] = r0; Bh[0][1] = r1; Bh[1][0] = r2; Bh[1][1] = r3;
                LDM_X4(r0, r1, r2, r3, tBh + b0 + 16 * 128);
                Bh[2][0] = r0; Bh[2][1] = r1; Bh[3][0] = r2; Bh[3][1] = r3;
                LDM_X4(r0, r1, r2, r3, tBl + b0);
                Bl[0][0] = r0; Bl[0][1] = r1; Bl[1][0] = r2; Bl[1][1] = r3;
                LDM_X4(r0, r1, r2, r3, tBl + b0 + 16 * 128);
                Bl[2][0] = r0; Bl[2][1] = r1; Bl[3][0] = r2; Bl[3][1] = r3;
            }
            // ---- 48 MMAs: hi*hi + hi*lo + lo*hi ----
#pragma unroll
            for (int mi = 0; mi < 4; mi++)
#pragma unroll
                for (int nj = 0; nj < 4; nj++) {
                    MMA16816(acc[mi][nj], Ah[mi], Bh[nj]);
                    MMA16816(acc[mi][nj], Ah[mi], Bl[nj]);
                    MMA16816(acc[mi][nj], Al[mi], Bh[nj]);
                }
        }
        __syncthreads();
    }

    // ---- epilogue: fragments straight to gmem ----
    const int g = lane >> 2, tig = lane & 3;
    auto stc = [&](int m, int n, float val) {
        if (n >= gz.N) return;
        if (gz.bias) val += gz.bias[n];
        if (gz.mode == 1) val = fmaxf(val, 0.f);
        if (gz.mode == 2) {
            int tt = m / B_, bb = m % B_;
            gz.C[((size_t)bb * MAXLEN + tt) * gz.ldc + n] = val * p.mask[m];
        } else {
            gz.C[(size_t)m * gz.ldc + n] = val;
        }
    };
#pragma unroll
    for (int mi = 0; mi < 4; mi++)
#pragma unroll
        for (int nj = 0; nj < 4; nj++) {
            int row = bm0 + wm * 64 + mi * 16 + g;
            int col = bn0 + wn * 32 + nj * 8 + 2 * tig;
            stc(row,     col,     acc[mi][nj][0]);
            stc(row,     col + 1, acc[mi][nj][1]);
            stc(row + 8, col,     acc[mi][nj][2]);
            stc(row + 8, col + 1, acc[mi][nj][3]);
        }
}

// -------------------- SIMT f32x2 GEMM (NN precompute only) ------------------
__device__ __forceinline__ void ffma2(ull& d, ull a, ull b) {
    asm("fma.rn.f32x2 %0, %1, %2, %0;" : "+l"(d) : "l"(a), "l"(b));
}
__device__ __forceinline__ float2 unpk(ull v) {
    float2 r; asm("mov.b64 {%0, %1}, %2;" : "=f"(r.x), "=f"(r.y) : "l"(v)); return r;
}
struct GemmZ {
    const float* A; const float* W; float* C;
    int lda, ldw, ldc, M, N, K;
};
struct GemmP { GemmZ z[2]; };

static inline GemmZ mkg(const float* A, int lda, const float* W, int ldw,
                        float* C, int ldc, int M, int N, int K)
{
    GemmZ z; z.A = A; z.W = W; z.C = C;
    z.lda = lda; z.ldw = ldw; z.ldc = ldc; z.M = M; z.N = N; z.K = K;
    return z;
}

// NN: C[m,n] = sum_k A[m,k] * W[k,n]
__global__ void __launch_bounds__(256, 2) gemm_nn(GemmP p)
{
    const GemmZ gz = p.z[blockIdx.z];
    const int bn0 = blockIdx.x * 128;
    const int bm0 = blockIdx.y * 128;
    if (bm0 >= gz.M) return;
    const int tid = threadIdx.x;

    __shared__ float As[16][256];
    __shared__ float Bs[16][128];
    const int tx = tid & 15, ty = tid >> 4;

    float4 pa[2], pb[2];
    const float* Abase = gz.A + (size_t)bm0 * gz.lda;
#pragma unroll
    for (int f = 0; f < 2; f++) {
        int q = tid * 2 + f;
        int r = q >> 2, c4 = (q & 3) * 4;
        pa[f] = *(const float4*)(Abase + (size_t)r * gz.lda + c4);
        int rb = q / 32, cb = q % 32;
        pb[f] = *(const float4*)(gz.W + (size_t)rb * gz.ldw + bn0 + cb * 4);
    }

    ull acc[8][4];
#pragma unroll
    for (int i = 0; i < 8; i++)
#pragma unroll
        for (int j = 0; j < 4; j++) acc[i][j] = 0ULL;

    for (int k0 = 0; k0 < gz.K; k0 += 16) {
#pragma unroll
        for (int f = 0; f < 2; f++) {
            int q = tid * 2 + f;
            int r = q >> 2, c4 = (q & 3) * 4;
            As[c4 + 0][2*r] = pa[f].x; As[c4 + 0][2*r+1] = pa[f].x;
            As[c4 + 1][2*r] = pa[f].y; As[c4 + 1][2*r+1] = pa[f].y;
            As[c4 + 2][2*r] = pa[f].z; As[c4 + 2][2*r+1] = pa[f].z;
            As[c4 + 3][2*r] = pa[f].w; As[c4 + 3][2*r+1] = pa[f].w;
            int rb = q / 32, cb = q % 32;
            *(float4*)&Bs[rb][cb * 4] = pb[f];
        }
        __syncthreads();
        if (k0 + 16 < gz.K) {
            const float* An = Abase + (k0 + 16);
            const float* Wn = gz.W + (size_t)(k0 + 16) * gz.ldw;
#pragma unroll
            for (int f = 0; f < 2; f++) {
                int q = tid * 2 + f;
                int r = q >> 2, c4 = (q & 3) * 4;
                pa[f] = *(const float4*)(An + (size_t)r * gz.lda + c4);
                int rb = q / 32, cb = q % 32;
                pb[f] = *(const float4*)(Wn + (size_t)rb * gz.ldw + bn0 + cb * 4);
            }
        }
#pragma unroll
        for (int kk = 0; kk < 16; kk++) {
            ull aa[8], bb[4];
            const float* arow = &As[kk][16 * ty];
            const float* browp = &Bs[kk][8 * tx];
#pragma unroll
            for (int i = 0; i < 8; i++) aa[i] = *(const ull*)(arow + 2 * i);
#pragma unroll
            for (int j = 0; j < 4; j++) bb[j] = *(const ull*)(browp + 2 * j);
#pragma unroll
            for (int i = 0; i < 8; i++)
#pragma unroll
                for (int j = 0; j < 4; j++) ffma2(acc[i][j], aa[i], bb[j]);
        }
        __syncthreads();
    }
#pragma unroll
    for (int i = 0; i < 8; i++) {
        int m = bm0 + ty * 8 + i;
#pragma unroll
        for (int j = 0; j < 4; j++) {
            float2 v = unpk(acc[i][j]);
            int n = bn0 + tx * 8 + 2 * j;
            gz.C[(size_t)m * gz.ldc + n]     = v.x;
            gz.C[(size_t)m * gz.ldc + n + 1] = v.y;
        }
    }
}

// ------------------------------- small kernels -----------------------------
__global__ void meta_kernel(const int* __restrict__ cap_len)
{
    int i = threadIdx.x;
    int ci = cap_len[i];
    int rank = 0;
    for (int j = 0; j < B_; j++) {
        int cj = cap_len[j];
        if (cj > ci || (cj == ci && j < i)) rank++;
    }
    g_order[rank] = i;
    __syncthreads();
    g_dl[i] = cap_len[g_order[i]] - 1;
    __syncthreads();
    int dli = g_dl[i];
    for (int t = 0; t < TT; t++) g_mask[t * B_ + i] = (t < dli) ? 1.f : 0.f;
}

__global__ void zero_init_kernel()
{
    int idx = blockIdx.x * 256 + threadIdx.x;
    if (idx < B_ * HID_) {
        g_h1[idx] = 0.f;    g_h1_h[idx] = __float2bfloat16(0.f); g_h1_l[idx] = __float2bfloat16(0.f);
        g_h2all[idx] = 0.f; g_h2_h[idx] = __float2bfloat16(0.f); g_h2_l[idx] = __float2bfloat16(0.f);
    }
}

__global__ void permute_v_kernel(const float* __restrict__ v)
{
    size_t idx = (size_t)blockIdx.x * 256 + threadIdx.x;
    if (idx >= (size_t)B_ * KOBJ * VD) return;
    int b = (int)(idx / ((size_t)KOBJ * VD));
    size_t rest = idx % ((size_t)KOBJ * VD);
    float x = v[(size_t)g_order[b] * KOBJ * VD + rest];
    g_vs[idx] = x;
    split2(x, g_vs_h[idx], g_vs_l[idx]);
}

__global__ void vmean_kernel()
{
    int idx = blockIdx.x * 256 + threadIdx.x;
    if (idx >= B_ * VD) return;
    int b = idx / VD, d = idx % VD;
    const float* p = g_vs + (size_t)b * KOBJ * VD + d;
    float s = 0.f;
#pragma unroll 6
    for (int k = 0; k < KOBJ; k++) s += p[(size_t)k * VD];
    g_vmean[idx] = s * (1.f / (float)KOBJ);
}

__global__ void build_x1c_kernel(const float* __restrict__ caption)
{
    size_t idx = (size_t)blockIdx.x * 256 + threadIdx.x;
    if (idx >= (size_t)TT * B_ * H3) return;
    int c = (int)(idx % H3);
    int r = (int)(idx / H3);
    int t = r / B_, b = r % B_;
    float val;
    if (c < VD) val = g_vmean[b * VD + c];
    else        val = caption[((size_t)g_order[b] * MAXLEN + t) * EMB + (c - VD)];
    split2(val, g_x1c_h[idx], g_x1c_l[idx]);
}

// generic fp32 -> bf16 hi/lo weight converter (with column offset + stride)
__global__ void convw_kernel(const float* __restrict__ src, int ld, int col0,
                             int rows, int cols, bf16* __restrict__ hi,
                             bf16* __restrict__ lo)
{
    size_t idx = (size_t)blockIdx.x * 256 + threadIdx.x;
    if (idx >= (size_t)rows * cols) return;
    int r = (int)(idx / cols), c = (int)(idx % cols);
    split2(src[(size_t)r * ld + col0 + c], hi[idx], lo[idx]);
}

__global__ void fusebias_kernel(const float* __restrict__ Wq,
                                const float* __restrict__ bq,
                                const float* __restrict__ b1,
                                const float* __restrict__ Wih2,
                                const float* __restrict__ bih2)
{
    int idx = blockIdx.x * 256 + threadIdx.x;
    if (idx < HID_) {
        const float* w = Wq + (size_t)idx * HID_;
        float s = 0.f;
        for (int j = 0; j < HID_; j++) s += w[j] * b1[j];
        g_bfq[idx] = s + bq[idx];
    } else if (idx < HID_ + H3) {
        int n = idx - HID_;
        const float* w = Wih2 + (size_t)n * H3 + VD;
        float s = 0.f;
        for (int j = 0; j < HID_; j++) s += w[j] * b1[j];
        g_bi2f[n] = s + bih2[n];
    }
}

// GRU pointwise; writes hout fp32 and bf16 hi/lo copies.
__global__ void gru_kernel(const float* __restrict__ gia,
                           const float* __restrict__ gib,
                           const float* __restrict__ biv,
                           const float* __restrict__ gh,
                           const float* __restrict__ hprev,
                           float* __restrict__ hout,
                           bf16* __restrict__ hout_h,
                           bf16* __restrict__ hout_l)
{
    int idx = blockIdx.x * 256 + threadIdx.x;
    if (idx >= B_ * HID_) return;
    int b = idx >> 10, j = idx & 1023;
    size_t base = (size_t)b * H3 + j;
    float gr = gia[base]            + gib[base];
    float gz = gia[base + HID_]     + gib[base + HID_];
    float gn = gia[base + 2 * HID_] + gib[base + 2 * HID_];
    if (biv) {
        gr += biv[j]; gz += biv[j + HID_]; gn += biv[j + 2 * HID_];
    }
    float r = 1.f / (1.f + expf(-(gr + gh[base])));
    float z = 1.f / (1.f + expf(-(gz + gh[base + HID_])));
    float n = tanhf(gn + r * gh[base + 2 * HID_]);
    float h = (1.f - z) * n + z * hprev[idx];
    hout[idx] = h;
    split2(h, hout_h[idx], hout_l[idx]);
}

// Attention: logits = vproj . (q*wa) + ba; softmax; masked alphas;
// att_v -> bf16 hi/lo.
__global__ void att_kernel(const float* __restrict__ wa,
                           const float* __restrict__ ba,
                           float* __restrict__ alphas, int t)
{
    int b = blockIdx.x, tid = threadIdx.x;
    __shared__ float qs[HID_];
    __shared__ float att[KOBJ];
    for (int d = tid; d < HID_; d += 256) qs[d] = g_q[b * HID_ + d] * wa[d];
    __syncthreads();

    int warp = tid >> 5, lane = tid & 31;
    for (int k = warp; k < KOBJ; k += 8) {
        const float* vp = g_vproj + ((size_t)b * KOBJ + k) * HID_;
        float s = 0.f;
        for (int d = lane; d < HID_; d += 32) s += vp[d] * qs[d];
#pragma unroll
        for (int o = 16; o; o >>= 1) s += __shfl_down_sync(0xffffffffu, s, o);
        if (lane == 0) att[k] = s + ba[0];
    }
    __syncthreads();

    if (tid == 0) {
        float mx = att[0];
        for (int k = 1; k < KOBJ; k++) mx = fmaxf(mx, att[k]);
        float ssum = 0.f;
        for (int k = 0; k < KOBJ; k++) { float e = expf(att[k] - mx); att[k] = e; ssum += e; }
        float inv = 1.f / ssum;
        for (int k = 0; k < KOBJ; k++) att[k] *= inv;
    }
    __syncthreads();

    if (tid < KOBJ) {
        float m = (t < g_dl[b]) ? 1.f : 0.f;
        alphas[((size_t)b * MAXLEN + t) * KOBJ + tid] = att[tid] * m;
    }
    for (int d = tid; d < VD; d += 256) {
        const float* vb = g_vs + (size_t)b * KOBJ * VD + d;
        float s = 0.f;
#pragma unroll 6
        for (int k = 0; k < KOBJ; k++) s += att[k] * vb[(size_t)k * VD];
        split2(s, g_attv_h[b * VD + d], g_attv_l[b * VD + d]);
    }
}

__global__ void zero_tails_kernel(float* __restrict__ predict,
                                  float* __restrict__ alphas)
{
    int idx = blockIdx.x * 256 + threadIdx.x;
    if (idx < B_ * NTOK) {
        int b = idx / NTOK, n = idx % NTOK;
        predict[((size_t)b * MAXLEN + (MAXLEN - 1)) * NTOK + n] = 0.f;
    } else if (idx < B_ * NTOK + B_ * KOBJ) {
        int r = idx - B_ * NTOK;
        int b = r / KOBJ, k = r % KOBJ;
        alphas[((size_t)b * MAXLEN + (MAXLEN - 1)) * KOBJ + k] = 0.f;
    }
}

// --------------------------------- launch ----------------------------------
static inline TZ mkt(const bf16* Ah, const bf16* Al, int lda,
                     const bf16* Wh, const bf16* Wl, int ldw,
                     float* C, int ldc, int M, int N, int K,
                     const float* bias, int mode)
{
    TZ z; z.Ahi = Ah; z.Alo = Al; z.Whi = Wh; z.Wlo = Wl;
    z.C = C; z.bias = bias; z.lda = lda; z.ldw = ldw; z.ldc = ldc;
    z.M = M; z.N = N; z.K = K; z.mode = mode;
    return z;
}

#define SYMADDR(var, sym) cudaGetSymbolAddress((void**)&var, sym)

extern "C" void kernel_launch(void* const* d_in, const int* in_sizes, int n_in,
                              void* d_out, int out_size)
{
    const float* v       = (const float*)d_in[0];
    const float* caption = (const float*)d_in[1];
    const int*   cap_len = (const int*)  d_in[2];
    const float* Wih1    = (const float*)d_in[3];
    const float* Whh1    = (const float*)d_in[4];
    const float* bih1    = (const float*)d_in[5];
    const float* bhh1    = (const float*)d_in[6];
    const float* Wih2    = (const float*)d_in[7];
    const float* Whh2    = (const float*)d_in[8];
    const float* bih2    = (const float*)d_in[9];
    const float* bhh2    = (const float*)d_in[10];
    const float* Wv      = (const float*)d_in[11];
    const float* bv      = (const float*)d_in[12];
    const float* Wq      = (const float*)d_in[13];
    const float* bq      = (const float*)d_in[14];
    const float* wa      = (const float*)d_in[15];
    const float* ba      = (const float*)d_in[16];
    const float* W1      = (const float*)d_in[17];
    const float* b1      = (const float*)d_in[18];
    const float* W2      = (const float*)d_in[19];
    const float* b2      = (const float*)d_in[20];

    float* out     = (float*)d_out;
    float* predict = out;
    float* alphas  = out + (size_t)B_ * MAXLEN * NTOK;

    // fp32 scratch addresses
    float *p_gi1c, *p_h1, *p_h2all, *p_gih, *p_gh1, *p_gh2, *p_q, *p_gi2h;
    float *p_p0, *p_Wfq, *p_Wf2h, *p_bfq, *p_bi2f, *p_mask, *p_vproj;
    SYMADDR(p_gi1c, g_gi1c);   SYMADDR(p_h1, g_h1);     SYMADDR(p_h2all, g_h2all);
    SYMADDR(p_gih, g_gih);     SYMADDR(p_gh1, g_gh1);   SYMADDR(p_gh2, g_gh2);
    SYMADDR(p_q, g_q);         SYMADDR(p_gi2h, g_gi2h); SYMADDR(p_p0, g_p0);
    SYMADDR(p_Wfq, g_Wfq);     SYMADDR(p_Wf2h, g_Wf2h); SYMADDR(p_bfq, g_bfq);
    SYMADDR(p_bi2f, g_bi2f);   SYMADDR(p_mask, g_mask); SYMADDR(p_vproj, g_vproj);

    // bf16 operand addresses
    bf16 *vs_h, *vs_l, *x1c_h, *x1c_l, *h1_h, *h1_l, *h2_h, *h2_l, *av_h, *av_l;
    bf16 *w1h_h, *w1h_l, *w1x_h, *w1x_l, *wh1_h, *wh1_l, *wh2_h, *wh2_l;
    bf16 *wv_h, *wv_l, *w2v_h, *w2v_l, *ww2_h, *ww2_l, *wfq_h, *wfq_l, *wf2_h, *wf2_l;
    SYMADDR(vs_h, g_vs_h);   SYMADDR(vs_l, g_vs_l);
    SYMADDR(x1c_h, g_x1c_h); SYMADDR(x1c_l, g_x1c_l);
    SYMADDR(h1_h, g_h1_h);   SYMADDR(h1_l, g_h1_l);
    SYMADDR(h2_h, g_h2_h);   SYMADDR(h2_l, g_h2_l);
    SYMADDR(av_h, g_attv_h); SYMADDR(av_l, g_attv_l);
    SYMADDR(w1h_h, g_wih1h_h); SYMADDR(w1h_l, g_wih1h_l);
    SYMADDR(w1x_h, g_wih1x_h); SYMADDR(w1x_l, g_wih1x_l);
    SYMADDR(wh1_h, g_whh1_h);  SYMADDR(wh1_l, g_whh1_l);
    SYMADDR(wh2_h, g_whh2_h);  SYMADDR(wh2_l, g_whh2_l);
    SYMADDR(wv_h, g_wv_h);     SYMADDR(wv_l, g_wv_l);
    SYMADDR(w2v_h, g_wih2v_h); SYMADDR(w2v_l, g_wih2v_l);
    SYMADDR(ww2_h, g_w2_h);    SYMADDR(ww2_l, g_w2_l);
    SYMADDR(wfq_h, g_wfq_h);   SYMADDR(wfq_l, g_wfq_l);
    SYMADDR(wf2_h, g_wf2h_h);  SYMADDR(wf2_l, g_wf2h_l);

    cudaFuncSetAttribute(tgemm_k, cudaFuncAttributeMaxDynamicSharedMemorySize,
                         TGSMEM);

    // ---- setup ----
    meta_kernel<<<1, B_>>>(cap_len);
    zero_init_kernel<<<(B_ * HID_ + 255) / 256, 256>>>();
    {
        size_t n = (size_t)B_ * KOBJ * VD;
        permute_v_kernel<<<(unsigned)((n + 255) / 256), 256>>>(v);
    }
    vmean_kernel<<<(B_ * VD + 255) / 256, 256>>>();
    {
        size_t n = (size_t)TT * B_ * H3;
        build_x1c_kernel<<<(unsigned)((n + 255) / 256), 256>>>(caption);
    }
    // weight conversions
    {
        auto cv = [](const float* s, int ld, int c0, int r, int c, bf16* h, bf16* l) {
            size_t n = (size_t)r * c;
            convw_kernel<<<(unsigned)((n + 255) / 256), 256>>>(s, ld, c0, r, c, h, l);
        };
        cv(Wih1, HID_ + VD + EMB, 0,    H3,   HID_, w1h_h, w1h_l);
        cv(Wih1, HID_ + VD + EMB, 1024, H3,   H3,   w1x_h, w1x_l);
        cv(Whh1, HID_,            0,    H3,   HID_, wh1_h, wh1_l);
        cv(Whh2, HID_,            0,    H3,   HID_, wh2_h, wh2_l);
        cv(Wv,   VD,              0,    HID_, VD,   wv_h,  wv_l);
        cv(Wih2, H3,              0,    H3,   VD,   w2v_h, w2v_l);
        cv(W2,   HID_,            0,    NTOK, HID_, ww2_h, ww2_l);
    }
    // precompute fused weights (SIMT NN), then convert + fused biases
    {
        GemmP P{};
        P.z[0] = mkg(Wq,        HID_, W1, HID_, p_Wfq,  HID_, HID_, HID_, HID_);
        P.z[1] = mkg(Wih2 + VD, H3,   W1, HID_, p_Wf2h, HID_, H3,   HID_, HID_);
        gemm_nn<<<dim3(HID_/128, H3/128, 2), 256>>>(P);
    }
    {
        auto cv = [](const float* s, int ld, int c0, int r, int c, bf16* h, bf16* l) {
            size_t n = (size_t)r * c;
            convw_kernel<<<(unsigned)((n + 255) / 256), 256>>>(s, ld, c0, r, c, h, l);
        };
        cv(p_Wfq,  HID_, 0, HID_, HID_, wfq_h, wfq_l);
        cv(p_Wf2h, HID_, 0, H3,   HID_, wf2_h, wf2_l);
    }
    fusebias_kernel<<<(HID_ + H3 + 255) / 256, 256>>>(Wq, bq, b1, Wih2, bih2);

    // ---- big tensor GEMMs ----
    {   // gi1c = X1c @ Wih1[:,1024:].T + bih1   [2432 x 3072 x K=3072]
        TP P{}; P.mask = nullptr;
        P.z[0] = mkt(x1c_h, x1c_l, H3, w1x_h, w1x_l, H3,
                     p_gi1c, H3, TT * B_, H3, H3, bih1, 0);
        tgemm_k<<<dim3(H3/64, (TT*B_)/128, 1), 128, TGSMEM>>>(P);
    }
    {   // vproj = relu(v_s @ Wv.T + bv)         [4608 x 1024 x K=2048]
        TP P{}; P.mask = nullptr;
        P.z[0] = mkt(vs_h, vs_l, VD, wv_h, wv_l, VD,
                     p_vproj, HID_, B_ * KOBJ, HID_, VD, bv, 1);
        tgemm_k<<<dim3(HID_/64, (B_*KOBJ)/128, 1), 128, TGSMEM>>>(P);
    }

    // ---- sequential decode ----
    const int gruBlocks = (B_ * HID_ + 255) / 256;
    for (int t = 0; t < TT; t++) {
        const bf16* h2p_h = h2_h + (size_t)t * B_ * HID_;
        const bf16* h2p_l = h2_l + (size_t)t * B_ * HID_;
        const float* h2prev = p_h2all + (size_t)t * B_ * HID_;
        float*       h2next = p_h2all + (size_t)(t + 1) * B_ * HID_;

        // stage1: gih = h2@Wih1h.T ; gh1 = h1@Whh1.T+bhh1 ; gh2 = h2@Whh2.T+bhh2
        {
            TP P{}; P.mask = nullptr;
            P.z[0] = mkt(h2p_h, h2p_l, HID_, w1h_h, w1h_l, HID_,
                         p_gih, H3, B_, H3, HID_, nullptr, 0);
            P.z[1] = mkt(h1_h, h1_l, HID_, wh1_h, wh1_l, HID_,
                         p_gh1, H3, B_, H3, HID_, bhh1, 0);
            P.z[2] = mkt(h2p_h, h2p_l, HID_, wh2_h, wh2_l, HID_,
                         p_gh2, H3, B_, H3, HID_, bhh2, 0);
            tgemm_k<<<dim3(H3/64, 1, 3), 128, TGSMEM>>>(P);
        }
        // GRU1 (h1 in place, + bf16 split out)
        gru_kernel<<<gruBlocks, 256>>>(p_gi1c + (size_t)t * B_ * H3, p_gih,
                                       nullptr, p_gh1, p_h1, p_h1, h1_h, h1_l);
        // stage2: q = relu(h1@Wfq.T + bfq) ; gi2h = h1@Wf2h.T
        {
            TP P{}; P.mask = nullptr;
            P.z[0] = mkt(h1_h, h1_l, HID_, wfq_h, wfq_l, HID_,
                         p_q, HID_, B_, HID_, HID_, p_bfq, 1);
            P.z[1] = mkt(h1_h, h1_l, HID_, wf2_h, wf2_l, HID_,
                         p_gi2h, H3, B_, H3, HID_, nullptr, 0);
            tgemm_k<<<dim3(H3/64, 1, 2), 128, TGSMEM>>>(P);
        }
        // attention
        att_kernel<<<B_, 256>>>(wa, ba, alphas, t);
        // gi2_att = att_v @ Wih2[:,:2048].T    [128 x 3072 x K=2048]
        {
            TP P{}; P.mask = nullptr;
            P.z[0] = mkt(av_h, av_l, VD, w2v_h, w2v_l, VD,
                         p_p0, H3, B_, H3, VD, nullptr, 0);
            tgemm_k<<<dim3(H3/64, 1, 1), 128, TGSMEM>>>(P);
        }
        // GRU2
        gru_kernel<<<gruBlocks, 256>>>(p_p0, p_gi2h, p_bi2f, p_gh2, h2prev,
                                       h2next,
                                       h2_h + (size_t)(t+1) * B_ * HID_,
                                       h2_l + (size_t)(t+1) * B_ * HID_);
    }

    // words = H2all @ W2.T + b2 (masked scatter)  [2432 x 10000 x K=1024]
    {
        TP P{}; P.mask = p_mask;
        P.z[0] = mkt(h2_h + B_ * HID_, h2_l + B_ * HID_, HID_,
                     ww2_h, ww2_l, HID_,
                     predict, NTOK, TT * B_, NTOK, HID_, b2, 2);
        tgemm_k<<<dim3((NTOK + 63) / 64, (TT*B_)/128, 1), 128, TGSMEM>>>(P);
    }
    zero_tails_kernel<<<(B_ * NTOK + B_ * KOBJ + 255) / 256, 256>>>(predict, alphas);
}